// round 1
// baseline (speedup 1.0000x reference)
#include <cuda_runtime.h>
#include <math.h>

#define BATCH 8
#define SEQ   2048
#define DIM   512
#define BM    128
#define BN    128
#define BKK   16
#define NTILE (SEQ / BM)   // 16 row tiles per batch
#define NBLK  (BATCH * NTILE)

#define SQRT_INV_T 3.16227766016838f   // sqrt(1/0.1)
#define SHIFT      10.0f               // diagonal logit value (cos=1)/T
#define LAMBDA     0.5f

// scratch (allocation-free requirement): normalized+scaled latents, per-block partials
__device__ float g_ln[BATCH * SEQ * DIM];       // 32 MB
__device__ float g_partials[NBLK];

// ---------------------------------------------------------------------------
// Kernel 1: L2-normalize each row, fold sqrt(1/T) so GEMM yields logits.
// 128 threads per row, one float4 per thread (512 floats).
// ---------------------------------------------------------------------------
__global__ void normalize_kernel(const float* __restrict__ x) {
    const int row = blockIdx.x;            // 0 .. BATCH*SEQ-1
    const int t   = threadIdx.x;           // 0 .. 127
    const float4 v = reinterpret_cast<const float4*>(x + (size_t)row * DIM)[t];
    float ss = v.x * v.x + v.y * v.y + v.z * v.z + v.w * v.w;
    #pragma unroll
    for (int o = 16; o > 0; o >>= 1) ss += __shfl_xor_sync(0xffffffffu, ss, o);
    __shared__ float ws[4];
    if ((t & 31) == 0) ws[t >> 5] = ss;
    __syncthreads();
    const float tot = ws[0] + ws[1] + ws[2] + ws[3];
    const float inv = SQRT_INV_T / fmaxf(sqrtf(tot), 1e-8f);
    float4 o4;
    o4.x = v.x * inv; o4.y = v.y * inv; o4.z = v.z * inv; o4.w = v.w * inv;
    reinterpret_cast<float4*>(g_ln + (size_t)row * DIM)[t] = o4;
}

// ---------------------------------------------------------------------------
// Kernel 2: fused  (L Lᵀ) tile GEMM + off-diagonal sumexp/rowsum reduction.
// Block = 256 threads (16x16), each thread an 8x8 register tile.
// Grid = (NTILE, BATCH). Each block owns 128 rows, loops over all 16 col tiles.
// ---------------------------------------------------------------------------
__global__ __launch_bounds__(256, 2) void fused_kernel() {
    __shared__ float As[BKK][BM + 4];
    __shared__ float Bs[BKK][BN + 4];

    const int bi = blockIdx.y;              // batch
    const int i0 = blockIdx.x * BM;         // row tile origin
    const int tid = threadIdx.x;
    const int tx = tid & 15;                // col group
    const int ty = tid >> 4;                // row group

    const int lrow = tid >> 2;              // 0..63   (loader mapping)
    const int lk4  = (tid & 3) << 2;        // 0,4,8,12

    const float* __restrict__ base = g_ln + (size_t)bi * SEQ * DIM;
    const float* __restrict__ Abase = base + (size_t)i0 * DIM;

    float sumexp[8];
    float rowsum[8];
    #pragma unroll
    for (int m = 0; m < 8; ++m) { sumexp[m] = 0.f; rowsum[m] = 0.f; }

    for (int jt = 0; jt < SEQ / BN; ++jt) {
        const int j0 = jt * BN;
        const float* __restrict__ Bbase = base + (size_t)j0 * DIM;

        float acc[8][8];
        #pragma unroll
        for (int m = 0; m < 8; ++m)
            #pragma unroll
            for (int n = 0; n < 8; ++n) acc[m][n] = 0.f;

        for (int k0 = 0; k0 < DIM; k0 += BKK) {
            // stage tiles (transposed into [k][row] layout)
            #pragma unroll
            for (int r = 0; r < 2; ++r) {
                const int row = lrow + r * 64;
                float4 av = *reinterpret_cast<const float4*>(
                    Abase + (size_t)row * DIM + k0 + lk4);
                As[lk4 + 0][row] = av.x; As[lk4 + 1][row] = av.y;
                As[lk4 + 2][row] = av.z; As[lk4 + 3][row] = av.w;
                float4 bv = *reinterpret_cast<const float4*>(
                    Bbase + (size_t)row * DIM + k0 + lk4);
                Bs[lk4 + 0][row] = bv.x; Bs[lk4 + 1][row] = bv.y;
                Bs[lk4 + 2][row] = bv.z; Bs[lk4 + 3][row] = bv.w;
            }
            __syncthreads();

            #pragma unroll
            for (int kk = 0; kk < BKK; ++kk) {
                float a[8], b[8];
                #pragma unroll
                for (int m = 0; m < 8; m += 4) {
                    float4 t4 = *reinterpret_cast<const float4*>(&As[kk][ty * 8 + m]);
                    a[m + 0] = t4.x; a[m + 1] = t4.y; a[m + 2] = t4.z; a[m + 3] = t4.w;
                }
                #pragma unroll
                for (int n = 0; n < 8; n += 4) {
                    float4 t4 = *reinterpret_cast<const float4*>(&Bs[kk][tx * 8 + n]);
                    b[n + 0] = t4.x; b[n + 1] = t4.y; b[n + 2] = t4.z; b[n + 3] = t4.w;
                }
                #pragma unroll
                for (int m = 0; m < 8; ++m)
                    #pragma unroll
                    for (int n = 0; n < 8; ++n)
                        acc[m][n] = fmaf(a[m], b[n], acc[m][n]);
            }
            __syncthreads();
        }

        // consume tile: logits v = acc; skip diagonal
        #pragma unroll
        for (int m = 0; m < 8; ++m) {
            const int row = i0 + ty * 8 + m;
            float se = 0.f, rs = 0.f;
            #pragma unroll
            for (int n = 0; n < 8; ++n) {
                const int col = j0 + tx * 8 + n;
                const float v = acc[m][n];
                if (row != col) {
                    se += __expf(v - SHIFT);
                    rs += v;
                }
            }
            sumexp[m] += se;
            rowsum[m] += rs;
        }
    }

    // reduce across the 16 threads sharing each row (contiguous 16-lane groups)
    float local = 0.f;
    #pragma unroll
    for (int m = 0; m < 8; ++m) {
        float se = sumexp[m], rs = rowsum[m];
        #pragma unroll
        for (int o = 8; o > 0; o >>= 1) {
            se += __shfl_xor_sync(0xffffffffu, se, o);
            rs += __shfl_xor_sync(0xffffffffu, rs, o);
        }
        if (tx == 0)
            local += (float)(SEQ - 1) * (SHIFT + logf(se)) - rs;
    }

    __shared__ float red[16];
    if (tx == 0) red[ty] = local;
    __syncthreads();
    if (tid == 0) {
        float s = 0.f;
        #pragma unroll
        for (int g = 0; g < 16; ++g) s += red[g];
        g_partials[bi * NTILE + blockIdx.x] = s;
    }
}

// ---------------------------------------------------------------------------
// Kernel 3: deterministic final reduction of NBLK (=128) partials.
// ---------------------------------------------------------------------------
__global__ void finalize_kernel(float* __restrict__ out) {
    const int t = threadIdx.x;              // 128 threads
    float v = g_partials[t];
    #pragma unroll
    for (int o = 16; o > 0; o >>= 1) v += __shfl_xor_sync(0xffffffffu, v, o);
    __shared__ float ws[4];
    if ((t & 31) == 0) ws[t >> 5] = v;
    __syncthreads();
    if (t == 0) {
        const float total = ws[0] + ws[1] + ws[2] + ws[3];
        const float scale = LAMBDA / ((float)BATCH * (float)SEQ * (float)SEQ);
        out[0] = total * scale;
    }
}

extern "C" void kernel_launch(void* const* d_in, const int* in_sizes, int n_in,
                              void* d_out, int out_size) {
    (void)in_sizes; (void)n_in; (void)out_size;
    const float* x = (const float*)d_in[0];
    float* out = (float*)d_out;

    normalize_kernel<<<BATCH * SEQ, 128>>>(x);
    fused_kernel<<<dim3(NTILE, BATCH), 256>>>();
    finalize_kernel<<<1, 128>>>(out);
}

// round 4
// speedup vs baseline: 5.8023x; 5.8023x over previous
#include <cuda_runtime.h>
#include <cuda_bf16.h>
#include <cstdint>
#include <math.h>

#define BATCH 8
#define SEQ   2048
#define DIM   512
#define BM    128
#define BN    128
#define BK    32
#define NJ    (SEQ / BN)     // 16 col tiles
#define NKC   (DIM / BK)     // 16 k-steps
#define NTILE (SEQ / BM)     // 16 row tiles
#define NBLK  (BATCH * NTILE)

#define SQRT_INV_T 3.16227766016838f
#define SHIFT      10.0f
#define LAMBDA     0.5f

// padded smem row stride: 32 bf16 + 8 pad = 40 bf16 = 80 B (conflict-free LDSM)
#define RSTRIDE    80
#define ATILE_B    (BM * RSTRIDE)            // 10240 B per k-chunk tile
#define SM_A       0
#define SM_B       (16 * ATILE_B)            // 163840
#define SMEM_TOTAL (SM_B + 2 * ATILE_B)      // 184320

__device__ __nv_bfloat16 g_lb[BATCH * SEQ * DIM];   // 16 MB scratch
__device__ float g_partials[NBLK];

// ---------------------------------------------------------------------------
__device__ __forceinline__ uint32_t smem_u32(const void* p) {
    uint32_t a;
    asm("{ .reg .u64 t; cvta.to.shared.u64 t, %1; cvt.u32.u64 %0, t; }"
        : "=r"(a) : "l"(p));
    return a;
}
#define CP16(d, s) \
    asm volatile("cp.async.cg.shared.global [%0], [%1], 16;" :: "r"(d), "l"(s))
#define CP_COMMIT() asm volatile("cp.async.commit_group;" ::: "memory")
#define CP_WAIT(n)  asm volatile("cp.async.wait_group %0;" :: "n"(n) : "memory")

__device__ __forceinline__ void ldsm4(uint32_t* r, uint32_t addr) {
    asm volatile("ldmatrix.sync.aligned.m8n8.x4.shared.b16 {%0,%1,%2,%3}, [%4];"
                 : "=r"(r[0]), "=r"(r[1]), "=r"(r[2]), "=r"(r[3]) : "r"(addr));
}
__device__ __forceinline__ void mma16816(float* d, const uint32_t* a,
                                         const uint32_t* b) {
    asm volatile(
        "mma.sync.aligned.m16n8k16.row.col.f32.bf16.bf16.f32 "
        "{%0,%1,%2,%3}, {%4,%5,%6,%7}, {%8,%9}, {%0,%1,%2,%3};"
        : "+f"(d[0]), "+f"(d[1]), "+f"(d[2]), "+f"(d[3])
        : "r"(a[0]), "r"(a[1]), "r"(a[2]), "r"(a[3]), "r"(b[0]), "r"(b[1]));
}

// ---------------------------------------------------------------------------
// Kernel 1: L2-normalize rows, fold sqrt(1/T), emit bf16.
// ---------------------------------------------------------------------------
__global__ void normalize_kernel(const float* __restrict__ x) {
    const int row = blockIdx.x;
    const int t   = threadIdx.x;                 // 0..127
    const float4 v = reinterpret_cast<const float4*>(x + (size_t)row * DIM)[t];
    float ss = fmaf(v.x, v.x, fmaf(v.y, v.y, fmaf(v.z, v.z, v.w * v.w)));
    #pragma unroll
    for (int o = 16; o > 0; o >>= 1) ss += __shfl_xor_sync(0xffffffffu, ss, o);
    __shared__ float ws[4];
    if ((t & 31) == 0) ws[t >> 5] = ss;
    __syncthreads();
    const float tot = ws[0] + ws[1] + ws[2] + ws[3];
    const float inv = SQRT_INV_T / fmaxf(sqrtf(tot), 1e-8f);
    __nv_bfloat162 lo = __floats2bfloat162_rn(v.x * inv, v.y * inv);
    __nv_bfloat162 hi = __floats2bfloat162_rn(v.z * inv, v.w * inv);
    uint2 o2;
    o2.x = *reinterpret_cast<uint32_t*>(&lo);
    o2.y = *reinterpret_cast<uint32_t*>(&hi);
    reinterpret_cast<uint2*>(g_lb + (size_t)row * DIM)[t] = o2;
}

// ---------------------------------------------------------------------------
// Kernel 2: bf16 HMMA Gram GEMM + fused off-diagonal sumexp/rowsum.
// 256 threads = 8 warps (4 x 2), warp tile 32x64. A resident, B double-buffered.
// Row sums are split over warp pairs (warp_n=0/1) and merged in smem BEFORE log.
// ---------------------------------------------------------------------------
__global__ void __launch_bounds__(256, 1) fused_mma_kernel() {
    extern __shared__ char smem[];
    const uint32_t sb  = smem_u32(smem);
    const int tid  = threadIdx.x;
    const int wid  = tid >> 5;
    const int lane = tid & 31;
    const int warp_m = wid >> 1;            // 0..3  (32 rows each)
    const int warp_n = wid & 1;             // 0..1  (64 cols each)
    const int bi = blockIdx.y;
    const int i0 = blockIdx.x * BM;

    const int g   = lane >> 2;              // group id 0..7 (row within 8)
    const int tig = lane & 3;               // thread in group (col pair)

    const __nv_bfloat16* __restrict__ base = g_lb + (size_t)bi * SEQ * DIM;
    const __nv_bfloat16* __restrict__ Ab   = base + (size_t)i0 * DIM;

    // ---- stage full A tile (128 x 512) into 16 k-chunk smem tiles ----
    for (int t = tid; t < 8192; t += 256) {           // 16B pieces
        const int r  = t >> 6;                        // row 0..127
        const int cg = t & 63;                        // global 16B chunk
        const uint32_t dst = sb + SM_A + (cg >> 2) * ATILE_B
                           + r * RSTRIDE + (cg & 3) * 16;
        CP16(dst, Ab + (size_t)r * DIM + cg * 8);
    }
    CP_COMMIT();

    // ldmatrix lane address components
    const int arow = (lane & 7) + ((lane >> 3) & 1) * 8;
    const int akc  = (lane >> 4) & 1;
    const int brow = (lane & 7) + ((lane >> 4) & 1) * 8;
    const int bkc  = (lane >> 3) & 1;

    float se[4], rs[4];
    #pragma unroll
    for (int s = 0; s < 4; ++s) { se[s] = 0.f; rs[s] = 0.f; }

    CP_WAIT(0);
    __syncthreads();

    for (int jt = 0; jt < NJ; ++jt) {
        const int j0 = jt * BN;
        const __nv_bfloat16* __restrict__ Bb = base + (size_t)j0 * DIM;

        float acc[2][8][4];
        #pragma unroll
        for (int mt = 0; mt < 2; ++mt)
            #pragma unroll
            for (int nt = 0; nt < 8; ++nt)
                #pragma unroll
                for (int i = 0; i < 4; ++i) acc[mt][nt][i] = 0.f;

        // prologue: load B k-chunk 0 into buffer 0
        {
            const int t2 = tid << 1;                  // 2 pieces per thread
            #pragma unroll
            for (int u = 0; u < 2; ++u) {
                const int t = t2 + u;                 // 0..511
                const int r = t >> 2, c = t & 3;
                CP16(sb + SM_B + r * RSTRIDE + c * 16,
                     Bb + (size_t)r * DIM + c * 8);
            }
            CP_COMMIT();
        }

        for (int kc = 0; kc < NKC; ++kc) {
            if (kc + 1 < NKC) {
                const uint32_t bdst = sb + SM_B + ((kc + 1) & 1) * ATILE_B;
                const int t2 = tid << 1;
                #pragma unroll
                for (int u = 0; u < 2; ++u) {
                    const int t = t2 + u;
                    const int r = t >> 2, c = t & 3;
                    CP16(bdst + r * RSTRIDE + c * 16,
                         Bb + (size_t)r * DIM + (kc + 1) * BK + c * 8);
                }
                CP_COMMIT();
                CP_WAIT(1);
            } else {
                CP_WAIT(0);
            }
            __syncthreads();

            const uint32_t abase = sb + SM_A + kc * ATILE_B;
            const uint32_t bbase = sb + SM_B + (kc & 1) * ATILE_B;

            #pragma unroll
            for (int ks = 0; ks < 2; ++ks) {
                uint32_t af[2][4];
                #pragma unroll
                for (int mt = 0; mt < 2; ++mt)
                    ldsm4(af[mt], abase
                          + (warp_m * 32 + mt * 16 + arow) * RSTRIDE
                          + (ks * 16 + akc * 8) * 2);
                uint32_t bf[4][4];
                #pragma unroll
                for (int p = 0; p < 4; ++p)
                    ldsm4(bf[p], bbase
                          + (warp_n * 64 + p * 16 + brow) * RSTRIDE
                          + (ks * 16 + bkc * 8) * 2);
                #pragma unroll
                for (int mt = 0; mt < 2; ++mt)
                    #pragma unroll
                    for (int nt = 0; nt < 8; ++nt)
                        mma16816(acc[mt][nt], af[mt], &bf[nt >> 1][(nt & 1) * 2]);
            }
            __syncthreads();
        }

        // ---- fused epilogue: fold this 128x(64) half-tile per warp ----
        const int row_base = i0 + warp_m * 32 + g;
        const int col_base = j0 + warp_n * 64 + tig * 2;
        #pragma unroll
        for (int mt = 0; mt < 2; ++mt)
            #pragma unroll
            for (int nt = 0; nt < 8; ++nt)
                #pragma unroll
                for (int i = 0; i < 4; ++i) {
                    const int row = row_base + mt * 16 + (i >> 1) * 8;
                    const int col = col_base + nt * 8 + (i & 1);
                    const float v = acc[mt][nt][i];
                    if (row != col) {
                        const int s = mt * 2 + (i >> 1);
                        se[s] += __expf(v - SHIFT);
                        rs[s] += v;
                    }
                }
    }

    // ---- reduce within quad (4 lanes sharing a row within this warp) ----
    #pragma unroll
    for (int s = 0; s < 4; ++s) {
        #pragma unroll
        for (int o = 1; o < 4; o <<= 1) {
            se[s] += __shfl_xor_sync(0xffffffffu, se[s], o);
            rs[s] += __shfl_xor_sync(0xffffffffu, rs[s], o);
        }
    }

    // ---- merge the two half-row warps (same warp_m, warp_n=0/1) BEFORE log ----
    __shared__ float se_red[8][8][4];   // [wid][g][s]
    __shared__ float rs_red[8][8][4];
    __shared__ float cred[4];
    if (tig == 0) {
        #pragma unroll
        for (int s = 0; s < 4; ++s) {
            se_red[wid][g][s] = se[s];
            rs_red[wid][g][s] = rs[s];
        }
    }
    __syncthreads();

    float contrib = 0.f;
    if (tid < 128) {
        const int wm = tid >> 5;         // 0..3
        const int gg = (tid >> 2) & 7;   // 0..7
        const int ss = tid & 3;          // 0..3
        const float set = se_red[wm * 2][gg][ss] + se_red[wm * 2 + 1][gg][ss];
        const float rst = rs_red[wm * 2][gg][ss] + rs_red[wm * 2 + 1][gg][ss];
        contrib = (float)(SEQ - 1) * (SHIFT + logf(set)) - rst;
    }
    #pragma unroll
    for (int o = 16; o > 0; o >>= 1)
        contrib += __shfl_xor_sync(0xffffffffu, contrib, o);
    if (tid < 128 && lane == 0) cred[wid] = contrib;
    __syncthreads();
    if (tid == 0)
        g_partials[bi * NTILE + blockIdx.x] = cred[0] + cred[1] + cred[2] + cred[3];
}

// ---------------------------------------------------------------------------
// Kernel 3: deterministic final reduction.
// ---------------------------------------------------------------------------
__global__ void finalize_kernel(float* __restrict__ out) {
    const int t = threadIdx.x;
    float v = g_partials[t];
    #pragma unroll
    for (int o = 16; o > 0; o >>= 1) v += __shfl_xor_sync(0xffffffffu, v, o);
    __shared__ float ws[4];
    if ((t & 31) == 0) ws[t >> 5] = v;
    __syncthreads();
    if (t == 0) {
        const float total = ws[0] + ws[1] + ws[2] + ws[3];
        out[0] = total * (LAMBDA / ((float)BATCH * (float)SEQ * (float)SEQ));
    }
}

extern "C" void kernel_launch(void* const* d_in, const int* in_sizes, int n_in,
                              void* d_out, int out_size) {
    (void)in_sizes; (void)n_in; (void)out_size;
    const float* x = (const float*)d_in[0];
    float* out = (float*)d_out;

    cudaFuncSetAttribute(fused_mma_kernel,
                         cudaFuncAttributeMaxDynamicSharedMemorySize, SMEM_TOTAL);

    normalize_kernel<<<BATCH * SEQ, 128>>>(x);
    fused_mma_kernel<<<dim3(NTILE, BATCH), 256, SMEM_TOTAL>>>();
    finalize_kernel<<<1, 128>>>(out);
}

// round 6
// speedup vs baseline: 9.3725x; 1.6153x over previous
#include <cuda_runtime.h>
#include <cuda_bf16.h>
#include <cstdint>
#include <math.h>

#define BATCH 8
#define SEQ   2048
#define DIM   512
#define BM    128
#define BN    128
#define BK    32
#define NKC   (DIM / BK)     // 16 k-steps
#define NTILE (SEQ / BM)     // 16 row blocks
#define NBLK  (BATCH * NTILE)

#define SQRT_INV_T 3.16227766016838f
#define SHIFT      10.0f
#define LAMBDA     0.5f

// padded smem row stride: 32 bf16 + 8 pad = 40 bf16 = 80 B (conflict-free LDSM)
#define RSTRIDE    80
#define ATILE_B    (BM * RSTRIDE)            // 10240 B per k-chunk tile
#define SM_A       0
#define SM_B       (16 * ATILE_B)            // 163840
#define SMEM_TOTAL (SM_B + 2 * ATILE_B)      // 184320

__device__ __nv_bfloat16 g_lb[BATCH * SEQ * DIM];   // 16 MB scratch
// symmetric-partials scratch: single-writer slots (deterministic)
__device__ float g_rse[BATCH][NTILE][BM];           // row-side sumexp
__device__ float g_rrs[BATCH][NTILE][BM];           // row-side rowsum
__device__ float g_cse[BATCH][NTILE][8][BM];        // col-side sumexp, slot d-1
__device__ float g_crs[BATCH][NTILE][8][BM];
__device__ float g_partials[NBLK];

// ---------------------------------------------------------------------------
__device__ __forceinline__ uint32_t smem_u32(const void* p) {
    uint32_t a;
    asm("{ .reg .u64 t; cvta.to.shared.u64 t, %1; cvt.u32.u64 %0, t; }"
        : "=r"(a) : "l"(p));
    return a;
}
#define CP16(d, s) \
    asm volatile("cp.async.cg.shared.global [%0], [%1], 16;" :: "r"(d), "l"(s))
#define CP_COMMIT() asm volatile("cp.async.commit_group;" ::: "memory")
#define CP_WAIT(n)  asm volatile("cp.async.wait_group %0;" :: "n"(n) : "memory")

__device__ __forceinline__ void ldsm4(uint32_t* r, uint32_t addr) {
    asm volatile("ldmatrix.sync.aligned.m8n8.x4.shared.b16 {%0,%1,%2,%3}, [%4];"
                 : "=r"(r[0]), "=r"(r[1]), "=r"(r[2]), "=r"(r[3]) : "r"(addr));
}
__device__ __forceinline__ void mma16816(float* d, const uint32_t* a,
                                         const uint32_t* b) {
    asm volatile(
        "mma.sync.aligned.m16n8k16.row.col.f32.bf16.bf16.f32 "
        "{%0,%1,%2,%3}, {%4,%5,%6,%7}, {%8,%9}, {%0,%1,%2,%3};"
        : "+f"(d[0]), "+f"(d[1]), "+f"(d[2]), "+f"(d[3])
        : "r"(a[0]), "r"(a[1]), "r"(a[2]), "r"(a[3]), "r"(b[0]), "r"(b[1]));
}

// ---------------------------------------------------------------------------
// Kernel 1: L2-normalize rows, fold sqrt(1/T), emit bf16.
// ---------------------------------------------------------------------------
__global__ void normalize_kernel(const float* __restrict__ x) {
    const int row = blockIdx.x;
    const int t   = threadIdx.x;                 // 0..127
    const float4 v = reinterpret_cast<const float4*>(x + (size_t)row * DIM)[t];
    float ss = fmaf(v.x, v.x, fmaf(v.y, v.y, fmaf(v.z, v.z, v.w * v.w)));
    #pragma unroll
    for (int o = 16; o > 0; o >>= 1) ss += __shfl_xor_sync(0xffffffffu, ss, o);
    __shared__ float ws[4];
    if ((t & 31) == 0) ws[t >> 5] = ss;
    __syncthreads();
    const float tot = ws[0] + ws[1] + ws[2] + ws[3];
    const float inv = SQRT_INV_T / fmaxf(sqrtf(tot), 1e-8f);
    __nv_bfloat162 lo = __floats2bfloat162_rn(v.x * inv, v.y * inv);
    __nv_bfloat162 hi = __floats2bfloat162_rn(v.z * inv, v.w * inv);
    uint2 o2;
    o2.x = *reinterpret_cast<uint32_t*>(&lo);
    o2.y = *reinterpret_cast<uint32_t*>(&hi);
    reinterpret_cast<uint2*>(g_lb + (size_t)row * DIM)[t] = o2;
}

// ---------------------------------------------------------------------------
// Kernel 2: symmetric bf16 HMMA Gram GEMM + fused two-sided fold.
// CTA(i,b): row-block i resident; col-blocks j=(i+d)%16, d=0..(i<8?8:7).
// Off-diagonal tiles fold rows (row-side, local regs) AND cols (col-side,
// shfl+smem reduce, single-writer STG to g_cse/g_crs slot d-1 of block j).
// ---------------------------------------------------------------------------
__global__ void __launch_bounds__(256, 1) fused_mma_kernel() {
    extern __shared__ char smem[];
    const uint32_t sb  = smem_u32(smem);
    const int tid  = threadIdx.x;
    const int wid  = tid >> 5;
    const int lane = tid & 31;
    const int warp_m = wid >> 1;            // 0..3  (32 rows each)
    const int warp_n = wid & 1;             // 0..1  (64 cols each)
    const int bi = blockIdx.y;
    const int it = blockIdx.x;              // row block 0..15
    const int i0 = it * BM;
    const int njt = (it < 8) ? 9 : 8;

    const int g   = lane >> 2;              // row group 0..7
    const int tig = lane & 3;               // col pair 0..3

    const __nv_bfloat16* __restrict__ base = g_lb + (size_t)bi * SEQ * DIM;
    const __nv_bfloat16* __restrict__ Ab   = base + (size_t)i0 * DIM;

    // ---- stage full A tile (128 x 512) into 16 k-chunk smem tiles ----
    for (int t = tid; t < 8192; t += 256) {           // 16B pieces
        const int r  = t >> 6;
        const int cg = t & 63;
        const uint32_t dst = sb + SM_A + (cg >> 2) * ATILE_B
                           + r * RSTRIDE + (cg & 3) * 16;
        CP16(dst, Ab + (size_t)r * DIM + cg * 8);
    }
    CP_COMMIT();

    const int arow = (lane & 7) + ((lane >> 3) & 1) * 8;
    const int akc  = (lane >> 4) & 1;
    const int brow = (lane & 7) + ((lane >> 4) & 1) * 8;
    const int bkc  = (lane >> 3) & 1;

    float se[4], rs[4];
    #pragma unroll
    for (int s = 0; s < 4; ++s) { se[s] = 0.f; rs[s] = 0.f; }

    __shared__ float smc[2][8][64];         // col-side cross-warp stage
    __shared__ float se_red[8][8][4];       // row-side warp_n merge
    __shared__ float rs_red[8][8][4];

    CP_WAIT(0);
    __syncthreads();

    for (int m = 0; m < njt; ++m) {
        const int j = (it + m) & 15;
        const __nv_bfloat16* __restrict__ Bb = base + (size_t)(j * BN) * DIM;

        float acc[2][8][4];
        #pragma unroll
        for (int mt = 0; mt < 2; ++mt)
            #pragma unroll
            for (int nt = 0; nt < 8; ++nt)
                #pragma unroll
                for (int i = 0; i < 4; ++i) acc[mt][nt][i] = 0.f;

        // prologue: B k-chunk 0 into buffer 0
        {
            const int t2 = tid << 1;
            #pragma unroll
            for (int u = 0; u < 2; ++u) {
                const int t = t2 + u;
                const int r = t >> 2, c = t & 3;
                CP16(sb + SM_B + r * RSTRIDE + c * 16,
                     Bb + (size_t)r * DIM + c * 8);
            }
            CP_COMMIT();
        }

        for (int kc = 0; kc < NKC; ++kc) {
            if (kc + 1 < NKC) {
                const uint32_t bdst = sb + SM_B + ((kc + 1) & 1) * ATILE_B;
                const int t2 = tid << 1;
                #pragma unroll
                for (int u = 0; u < 2; ++u) {
                    const int t = t2 + u;
                    const int r = t >> 2, c = t & 3;
                    CP16(bdst + r * RSTRIDE + c * 16,
                         Bb + (size_t)r * DIM + (kc + 1) * BK + c * 8);
                }
                CP_COMMIT();
                CP_WAIT(1);
            } else {
                CP_WAIT(0);
            }
            __syncthreads();

            const uint32_t abase = sb + SM_A + kc * ATILE_B;
            const uint32_t bbase = sb + SM_B + (kc & 1) * ATILE_B;

            #pragma unroll
            for (int ks = 0; ks < 2; ++ks) {
                uint32_t af[2][4];
                #pragma unroll
                for (int mt = 0; mt < 2; ++mt)
                    ldsm4(af[mt], abase
                          + (warp_m * 32 + mt * 16 + arow) * RSTRIDE
                          + (ks * 16 + akc * 8) * 2);
                uint32_t bf[4][4];
                #pragma unroll
                for (int p = 0; p < 4; ++p)
                    ldsm4(bf[p], bbase
                          + (warp_n * 64 + p * 16 + brow) * RSTRIDE
                          + (ks * 16 + bkc * 8) * 2);
                #pragma unroll
                for (int mt = 0; mt < 2; ++mt)
                    #pragma unroll
                    for (int nt = 0; nt < 8; ++nt)
                        mma16816(acc[mt][nt], af[mt], &bf[nt >> 1][(nt & 1) * 2]);
            }
            __syncthreads();
        }

        // ---- fused two-sided epilogue ----
        if (m == 0) {
            // diagonal tile: row-side only, skip diagonal elements
            #pragma unroll
            for (int mt = 0; mt < 2; ++mt)
                #pragma unroll
                for (int nt = 0; nt < 8; ++nt)
                    #pragma unroll
                    for (int i = 0; i < 4; ++i) {
                        const int lr = warp_m * 32 + mt * 16 + (i >> 1) * 8 + g;
                        const int lc = warp_n * 64 + nt * 8 + tig * 2 + (i & 1);
                        const float v = acc[mt][nt][i];
                        if (lr != lc) {
                            const int s = mt * 2 + (i >> 1);
                            se[s] += __expf(v - SHIFT);
                            rs[s] += v;
                        }
                    }
        } else {
            float cse[16], crs[16];
            #pragma unroll
            for (int q = 0; q < 16; ++q) { cse[q] = 0.f; crs[q] = 0.f; }
            #pragma unroll
            for (int mt = 0; mt < 2; ++mt)
                #pragma unroll
                for (int nt = 0; nt < 8; ++nt)
                    #pragma unroll
                    for (int i = 0; i < 4; ++i) {
                        const float v = acc[mt][nt][i];
                        const float e = __expf(v - SHIFT);
                        const int s = mt * 2 + (i >> 1);
                        se[s] += e;
                        rs[s] += v;
                        const int q = nt * 2 + (i & 1);
                        cse[q] += e;
                        crs[q] += v;
                    }
            // reduce col partials over the 8 row-groups (lane bits 2..4)
            #pragma unroll
            for (int q = 0; q < 16; ++q) {
                #pragma unroll
                for (int o = 4; o < 32; o <<= 1) {
                    cse[q] += __shfl_xor_sync(0xffffffffu, cse[q], o);
                    crs[q] += __shfl_xor_sync(0xffffffffu, crs[q], o);
                }
            }
            if (lane < 4) {      // lane == tig, g == 0
                #pragma unroll
                for (int nt = 0; nt < 8; ++nt)
                    #pragma unroll
                    for (int b2 = 0; b2 < 2; ++b2) {
                        smc[0][wid][nt * 8 + lane * 2 + b2] = cse[nt * 2 + b2];
                        smc[1][wid][nt * 8 + lane * 2 + b2] = crs[nt * 2 + b2];
                    }
            }
            __syncthreads();
            if (tid < BM) {      // combine warp_m quadrants, single-writer STG
                const int wn = tid >> 6, lc = tid & 63;
                float cs = 0.f, cr = 0.f;
                #pragma unroll
                for (int wm = 0; wm < 4; ++wm) {
                    cs += smc[0][wm * 2 + wn][lc];
                    cr += smc[1][wm * 2 + wn][lc];
                }
                g_cse[bi][j][m - 1][tid] = cs;
                g_crs[bi][j][m - 1][tid] = cr;
            }
        }
    }

    // ---- row-side: quad reduce, merge warp_n halves, store partials ----
    #pragma unroll
    for (int s = 0; s < 4; ++s) {
        #pragma unroll
        for (int o = 1; o < 4; o <<= 1) {
            se[s] += __shfl_xor_sync(0xffffffffu, se[s], o);
            rs[s] += __shfl_xor_sync(0xffffffffu, rs[s], o);
        }
    }
    __syncthreads();          // smc/last-tile readers done before se_red reuse
    if (tig == 0) {
        #pragma unroll
        for (int s = 0; s < 4; ++s) {
            se_red[wid][g][s] = se[s];
            rs_red[wid][g][s] = rs[s];
        }
    }
    __syncthreads();
    if (tid < BM) {
        const int wm = tid >> 5;
        const int gg = (tid >> 2) & 7;
        const int ss = tid & 3;
        const int row = wm * 32 + (ss >> 1) * 16 + (ss & 1) * 8 + gg;
        g_rse[bi][it][row] = se_red[wm * 2][gg][ss] + se_red[wm * 2 + 1][gg][ss];
        g_rrs[bi][it][row] = rs_red[wm * 2][gg][ss] + rs_red[wm * 2 + 1][gg][ss];
    }
}

// ---------------------------------------------------------------------------
// Kernel 3: per-row combine (row-side + col-side slots), log, block partials.
// ---------------------------------------------------------------------------
__global__ void finalize1_kernel() {
    const int k = blockIdx.x;       // row block
    const int b = blockIdx.y;
    const int r = threadIdx.x;      // 0..127
    float seT = g_rse[b][k][r];
    float rsT = g_rrs[b][k][r];
    const int nslots = (k >= 8) ? 8 : 7;
    for (int d = 0; d < nslots; ++d) {
        seT += g_cse[b][k][d][r];
        rsT += g_crs[b][k][d][r];
    }
    float contrib = (float)(SEQ - 1) * (SHIFT + logf(seT)) - rsT;
    #pragma unroll
    for (int o = 16; o > 0; o >>= 1)
        contrib += __shfl_xor_sync(0xffffffffu, contrib, o);
    __shared__ float ws[4];
    if ((r & 31) == 0) ws[r >> 5] = contrib;
    __syncthreads();
    if (r == 0)
        g_partials[b * NTILE + k] = ws[0] + ws[1] + ws[2] + ws[3];
}

// ---------------------------------------------------------------------------
// Kernel 4: deterministic final reduction.
// ---------------------------------------------------------------------------
__global__ void finalize2_kernel(float* __restrict__ out) {
    const int t = threadIdx.x;
    float v = g_partials[t];
    #pragma unroll
    for (int o = 16; o > 0; o >>= 1) v += __shfl_xor_sync(0xffffffffu, v, o);
    __shared__ float ws[4];
    if ((t & 31) == 0) ws[t >> 5] = v;
    __syncthreads();
    if (t == 0) {
        const float total = ws[0] + ws[1] + ws[2] + ws[3];
        out[0] = total * (LAMBDA / ((float)BATCH * (float)SEQ * (float)SEQ));
    }
}

extern "C" void kernel_launch(void* const* d_in, const int* in_sizes, int n_in,
                              void* d_out, int out_size) {
    (void)in_sizes; (void)n_in; (void)out_size;
    const float* x = (const float*)d_in[0];
    float* out = (float*)d_out;

    cudaFuncSetAttribute(fused_mma_kernel,
                         cudaFuncAttributeMaxDynamicSharedMemorySize, SMEM_TOTAL);

    normalize_kernel<<<BATCH * SEQ, 128>>>(x);
    fused_mma_kernel<<<dim3(NTILE, BATCH), 256, SMEM_TOTAL>>>();
    finalize1_kernel<<<dim3(NTILE, BATCH), 128>>>();
    finalize2_kernel<<<1, 128>>>(out);
}

// round 7
// speedup vs baseline: 10.2371x; 1.0922x over previous
#include <cuda_runtime.h>
#include <cuda_bf16.h>
#include <cstdint>
#include <math.h>

#define BATCH 8
#define SEQ   2048
#define DIM   512
#define BM    128
#define BN    128
#define NKP   8              // k pair-steps (64 cols each)
#define NTILE (SEQ / BM)     // 16 row blocks
#define NBLK  (BATCH * NTILE)

#define SQRT_INV_T 3.16227766016838f
#define SHIFT      10.0f
#define LAMBDA     0.5f

// padded smem row stride: 32 bf16 + 8 pad = 40 bf16 = 80 B (conflict-free LDSM)
#define RSTRIDE    80
#define ATILE_B    (BM * RSTRIDE)            // 10240 B per 32-col chunk tile
#define SM_A       0
#define SM_B       (16 * ATILE_B)            // 163840
#define SMEM_TOTAL (SM_B + 4 * ATILE_B)      // 204800 (B: 2 stages x 2 chunks)

__device__ __nv_bfloat16 g_lb[BATCH * SEQ * DIM];   // 16 MB scratch
// single-writer deterministic scratch
__device__ float g_rse[BATCH][NTILE][BM];           // row-side sumexp
__device__ float g_cse[BATCH][NTILE][8][BM];        // col-side sumexp, slot d-1
__device__ float g_cpart[BATCH][NTILE][DIM];        // column-sum partials
__device__ float g_partials[NBLK];
__device__ int   g_cnt;

// ---------------------------------------------------------------------------
__device__ __forceinline__ uint32_t smem_u32(const void* p) {
    uint32_t a;
    asm("{ .reg .u64 t; cvta.to.shared.u64 t, %1; cvt.u32.u64 %0, t; }"
        : "=r"(a) : "l"(p));
    return a;
}
#define CP16(d, s) \
    asm volatile("cp.async.cg.shared.global [%0], [%1], 16;" :: "r"(d), "l"(s))
#define CP_COMMIT() asm volatile("cp.async.commit_group;" ::: "memory")
#define CP_WAIT(n)  asm volatile("cp.async.wait_group %0;" :: "n"(n) : "memory")

__device__ __forceinline__ void ldsm4(uint32_t* r, uint32_t addr) {
    asm volatile("ldmatrix.sync.aligned.m8n8.x4.shared.b16 {%0,%1,%2,%3}, [%4];"
                 : "=r"(r[0]), "=r"(r[1]), "=r"(r[2]), "=r"(r[3]) : "r"(addr));
}
__device__ __forceinline__ void mma16816(float* d, const uint32_t* a,
                                         const uint32_t* b) {
    asm volatile(
        "mma.sync.aligned.m16n8k16.row.col.f32.bf16.bf16.f32 "
        "{%0,%1,%2,%3}, {%4,%5,%6,%7}, {%8,%9}, {%0,%1,%2,%3};"
        : "+f"(d[0]), "+f"(d[1]), "+f"(d[2]), "+f"(d[3])
        : "r"(a[0]), "r"(a[1]), "r"(a[2]), "r"(a[3]), "r"(b[0]), "r"(b[1]));
}

// ---------------------------------------------------------------------------
// Kernel 1: L2-normalize rows, fold sqrt(1/T), emit bf16.
// ---------------------------------------------------------------------------
__global__ void normalize_kernel(const float* __restrict__ x) {
    const int row = blockIdx.x;
    const int t   = threadIdx.x;                 // 0..127
    const float4 v = reinterpret_cast<const float4*>(x + (size_t)row * DIM)[t];
    float ss = fmaf(v.x, v.x, fmaf(v.y, v.y, fmaf(v.z, v.z, v.w * v.w)));
    #pragma unroll
    for (int o = 16; o > 0; o >>= 1) ss += __shfl_xor_sync(0xffffffffu, ss, o);
    __shared__ float ws[4];
    if ((t & 31) == 0) ws[t >> 5] = ss;
    __syncthreads();
    const float tot = ws[0] + ws[1] + ws[2] + ws[3];
    const float inv = SQRT_INV_T / fmaxf(sqrtf(tot), 1e-8f);
    __nv_bfloat162 lo = __floats2bfloat162_rn(v.x * inv, v.y * inv);
    __nv_bfloat162 hi = __floats2bfloat162_rn(v.z * inv, v.w * inv);
    uint2 o2;
    o2.x = *reinterpret_cast<uint32_t*>(&lo);
    o2.y = *reinterpret_cast<uint32_t*>(&hi);
    reinterpret_cast<uint2*>(g_lb + (size_t)row * DIM)[t] = o2;
}

// ---------------------------------------------------------------------------
// Kernel 2: symmetric bf16 HMMA Gram GEMM + fused two-sided sumexp fold.
// Rowsum is NOT accumulated (analytic via column-sum vector).
// k-loop processes 64-col pairs (2 chunks) per sync iteration.
// ---------------------------------------------------------------------------
__global__ void __launch_bounds__(256, 1) fused_mma_kernel() {
    extern __shared__ char smem[];
    const uint32_t sb  = smem_u32(smem);
    const int tid  = threadIdx.x;
    const int wid  = tid >> 5;
    const int lane = tid & 31;
    const int warp_m = wid >> 1;            // 0..3  (32 rows each)
    const int warp_n = wid & 1;             // 0..1  (64 cols each)
    const int bi = blockIdx.y;
    const int it = blockIdx.x;              // row block 0..15
    const int i0 = it * BM;
    const int njt = (it < 8) ? 9 : 8;

    const int g   = lane >> 2;              // row group 0..7
    const int tig = lane & 3;               // col pair 0..3

    const __nv_bfloat16* __restrict__ base = g_lb + (size_t)bi * SEQ * DIM;
    const __nv_bfloat16* __restrict__ Ab   = base + (size_t)i0 * DIM;

    // ---- stage full A tile (128 x 512) into 16 chunk smem tiles ----
    for (int t = tid; t < 8192; t += 256) {           // 16B pieces
        const int r  = t >> 6;
        const int cg = t & 63;
        const uint32_t dst = sb + SM_A + (cg >> 2) * ATILE_B
                           + r * RSTRIDE + (cg & 3) * 16;
        CP16(dst, Ab + (size_t)r * DIM + cg * 8);
    }
    CP_COMMIT();
    CP_WAIT(0);
    __syncthreads();

    // ---- column-sum partial of resident A rows (for analytic rowsum) ----
    for (int col = tid; col < DIM; col += 256) {
        float s = 0.f;
        const uint32_t cb = (uint32_t)(col >> 5) * ATILE_B + (col & 31) * 2;
        #pragma unroll 8
        for (int r = 0; r < BM; ++r)
            s += __bfloat162float(
                *reinterpret_cast<__nv_bfloat16*>(smem + cb + r * RSTRIDE));
        g_cpart[bi][it][col] = s;
    }

    const int arow = (lane & 7) + ((lane >> 3) & 1) * 8;
    const int akc  = (lane >> 4) & 1;
    const int brow = (lane & 7) + ((lane >> 4) & 1) * 8;
    const int bkc  = (lane >> 3) & 1;

    float se[4];
    #pragma unroll
    for (int s = 0; s < 4; ++s) se[s] = 0.f;

    __shared__ float smc[8][64];            // col-side cross-warp stage
    __shared__ float se_red[8][8][4];       // row-side warp_n merge

    for (int m = 0; m < njt; ++m) {
        const int j = (it + m) & 15;
        const __nv_bfloat16* __restrict__ Bb = base + (size_t)(j * BN) * DIM;

        float acc[2][8][4];
        #pragma unroll
        for (int mt = 0; mt < 2; ++mt)
            #pragma unroll
            for (int nt = 0; nt < 8; ++nt)
                #pragma unroll
                for (int i = 0; i < 4; ++i) acc[mt][nt][i] = 0.f;

        // prologue: pair 0 (chunks 0,1) into stage 0
        {
            #pragma unroll
            for (int u = 0; u < 4; ++u) {
                const int t = tid + u * 256;          // 0..1023
                const int cc = t >> 9, rem = t & 511;
                const int r = rem >> 2, c = rem & 3;
                CP16(sb + SM_B + cc * ATILE_B + r * RSTRIDE + c * 16,
                     Bb + (size_t)r * DIM + (size_t)(cc * 4 + c) * 8);
            }
            CP_COMMIT();
        }

        for (int kp = 0; kp < NKP; ++kp) {
            if (kp + 1 < NKP) {
                const uint32_t bdst = sb + SM_B + (((kp + 1) & 1) * 2) * ATILE_B;
                #pragma unroll
                for (int u = 0; u < 4; ++u) {
                    const int t = tid + u * 256;
                    const int cc = t >> 9, rem = t & 511;
                    const int r = rem >> 2, c = rem & 3;
                    CP16(bdst + cc * ATILE_B + r * RSTRIDE + c * 16,
                         Bb + (size_t)r * DIM
                            + (size_t)((kp + 1) * 8 + cc * 4 + c) * 8);
                }
                CP_COMMIT();
                CP_WAIT(1);
            } else {
                CP_WAIT(0);
            }
            __syncthreads();

            #pragma unroll
            for (int cc = 0; cc < 2; ++cc) {
                const uint32_t abase = sb + SM_A + (kp * 2 + cc) * ATILE_B;
                const uint32_t bbase = sb + SM_B + ((kp & 1) * 2 + cc) * ATILE_B;
                #pragma unroll
                for (int ks = 0; ks < 2; ++ks) {
                    uint32_t af[2][4];
                    #pragma unroll
                    for (int mt = 0; mt < 2; ++mt)
                        ldsm4(af[mt], abase
                              + (warp_m * 32 + mt * 16 + arow) * RSTRIDE
                              + (ks * 16 + akc * 8) * 2);
                    uint32_t bf[4][4];
                    #pragma unroll
                    for (int p = 0; p < 4; ++p)
                        ldsm4(bf[p], bbase
                              + (warp_n * 64 + p * 16 + brow) * RSTRIDE
                              + (ks * 16 + bkc * 8) * 2);
                    #pragma unroll
                    for (int mt = 0; mt < 2; ++mt)
                        #pragma unroll
                        for (int nt = 0; nt < 8; ++nt)
                            mma16816(acc[mt][nt], af[mt],
                                     &bf[nt >> 1][(nt & 1) * 2]);
                }
            }
            __syncthreads();
        }

        // ---- fused two-sided epilogue (sumexp only) ----
        if (m == 0) {
            #pragma unroll
            for (int mt = 0; mt < 2; ++mt)
                #pragma unroll
                for (int nt = 0; nt < 8; ++nt)
                    #pragma unroll
                    for (int i = 0; i < 4; ++i) {
                        const int lr = warp_m * 32 + mt * 16 + (i >> 1) * 8 + g;
                        const int lc = warp_n * 64 + nt * 8 + tig * 2 + (i & 1);
                        if (lr != lc)
                            se[mt * 2 + (i >> 1)] += __expf(acc[mt][nt][i] - SHIFT);
                    }
        } else {
            float cse[16];
            #pragma unroll
            for (int q = 0; q < 16; ++q) cse[q] = 0.f;
            #pragma unroll
            for (int mt = 0; mt < 2; ++mt)
                #pragma unroll
                for (int nt = 0; nt < 8; ++nt)
                    #pragma unroll
                    for (int i = 0; i < 4; ++i) {
                        const float e = __expf(acc[mt][nt][i] - SHIFT);
                        se[mt * 2 + (i >> 1)] += e;
                        cse[nt * 2 + (i & 1)] += e;
                    }
            #pragma unroll
            for (int q = 0; q < 16; ++q) {
                #pragma unroll
                for (int o = 4; o < 32; o <<= 1)
                    cse[q] += __shfl_xor_sync(0xffffffffu, cse[q], o);
            }
            if (lane < 4) {      // lane == tig, g == 0
                #pragma unroll
                for (int nt = 0; nt < 8; ++nt)
                    #pragma unroll
                    for (int b2 = 0; b2 < 2; ++b2)
                        smc[wid][nt * 8 + lane * 2 + b2] = cse[nt * 2 + b2];
            }
            __syncthreads();
            if (tid < BM) {      // combine warp_m quadrants, single-writer STG
                const int wn = tid >> 6, lc = tid & 63;
                float cs = 0.f;
                #pragma unroll
                for (int wm = 0; wm < 4; ++wm)
                    cs += smc[wm * 2 + wn][lc];
                g_cse[bi][j][m - 1][tid] = cs;
            }
            __syncthreads();     // protect smc for next tile
        }
    }

    // ---- row-side: quad reduce, merge warp_n halves, store partials ----
    #pragma unroll
    for (int s = 0; s < 4; ++s) {
        #pragma unroll
        for (int o = 1; o < 4; o <<= 1)
            se[s] += __shfl_xor_sync(0xffffffffu, se[s], o);
    }
    if (tig == 0) {
        #pragma unroll
        for (int s = 0; s < 4; ++s) se_red[wid][g][s] = se[s];
    }
    __syncthreads();
    if (tid < BM) {
        const int wm = tid >> 5;
        const int gg = (tid >> 2) & 7;
        const int ss = tid & 3;
        const int row = wm * 32 + (ss >> 1) * 16 + (ss & 1) * 8 + gg;
        g_rse[bi][it][row] = se_red[wm * 2][gg][ss] + se_red[wm * 2 + 1][gg][ss];
    }
}

// ---------------------------------------------------------------------------
// Kernel 3: merged finalize — column-sum vector, per-row seT + analytic
// rowsum (dot with c), log, block partial, counter-elected final reduce.
// ---------------------------------------------------------------------------
__global__ void finalize_kernel(float* __restrict__ out) {
    const int k = blockIdx.x;       // row block
    const int b = blockIdx.y;
    const int r = threadIdx.x;      // 0..127

    __shared__ float c[DIM];
    __shared__ float ws[4];
    __shared__ int   flag;

    // batch column-sum vector c_b (each block computes its own copy)
    for (int comp = r; comp < DIM; comp += 128) {
        float s = 0.f;
        #pragma unroll
        for (int p = 0; p < NTILE; ++p) s += g_cpart[b][p][comp];
        c[comp] = s;
    }
    __syncthreads();

    // total sumexp for this row
    float seT = g_rse[b][k][r];
    const int nslots = (k >= 8) ? 8 : 7;
    for (int d = 0; d < nslots; ++d) seT += g_cse[b][k][d][r];

    // analytic rowsum: <a_row, c> - SHIFT
    const __nv_bfloat16* __restrict__ a =
        g_lb + ((size_t)b * SEQ + (size_t)k * BM + r) * DIM;
    float dot = 0.f;
    #pragma unroll 8
    for (int q = 0; q < DIM / 8; ++q) {
        const uint4 u = __ldg(reinterpret_cast<const uint4*>(a) + q);
        const __nv_bfloat162 p0 = *reinterpret_cast<const __nv_bfloat162*>(&u.x);
        const __nv_bfloat162 p1 = *reinterpret_cast<const __nv_bfloat162*>(&u.y);
        const __nv_bfloat162 p2 = *reinterpret_cast<const __nv_bfloat162*>(&u.z);
        const __nv_bfloat162 p3 = *reinterpret_cast<const __nv_bfloat162*>(&u.w);
        const float* cb = c + q * 8;
        dot = fmaf(__bfloat162float(p0.x), cb[0], dot);
        dot = fmaf(__bfloat162float(p0.y), cb[1], dot);
        dot = fmaf(__bfloat162float(p1.x), cb[2], dot);
        dot = fmaf(__bfloat162float(p1.y), cb[3], dot);
        dot = fmaf(__bfloat162float(p2.x), cb[4], dot);
        dot = fmaf(__bfloat162float(p2.y), cb[5], dot);
        dot = fmaf(__bfloat162float(p3.x), cb[6], dot);
        dot = fmaf(__bfloat162float(p3.y), cb[7], dot);
    }

    float contrib = (float)(SEQ - 1) * (SHIFT + logf(seT)) - (dot - SHIFT);
    #pragma unroll
    for (int o = 16; o > 0; o >>= 1)
        contrib += __shfl_xor_sync(0xffffffffu, contrib, o);
    if ((r & 31) == 0) ws[r >> 5] = contrib;
    __syncthreads();
    if (r == 0) {
        g_partials[b * NTILE + k] = ws[0] + ws[1] + ws[2] + ws[3];
        __threadfence();
        const int t = atomicAdd(&g_cnt, 1);
        flag = (t == NBLK - 1) ? 1 : 0;
    }
    __syncthreads();

    if (flag) {
        __threadfence();
        float v = __ldcg(&g_partials[r]);
        #pragma unroll
        for (int o = 16; o > 0; o >>= 1)
            v += __shfl_xor_sync(0xffffffffu, v, o);
        if ((r & 31) == 0) ws[r >> 5] = v;
        __syncthreads();
        if (r == 0) {
            const float total = ws[0] + ws[1] + ws[2] + ws[3];
            out[0] = total * (LAMBDA / ((float)BATCH * (float)SEQ * (float)SEQ));
            g_cnt = 0;               // reset for next graph replay
        }
    }
}

extern "C" void kernel_launch(void* const* d_in, const int* in_sizes, int n_in,
                              void* d_out, int out_size) {
    (void)in_sizes; (void)n_in; (void)out_size;
    const float* x = (const float*)d_in[0];
    float* out = (float*)d_out;

    cudaFuncSetAttribute(fused_mma_kernel,
                         cudaFuncAttributeMaxDynamicSharedMemorySize, SMEM_TOTAL);

    normalize_kernel<<<BATCH * SEQ, 128>>>(x);
    fused_mma_kernel<<<dim3(NTILE, BATCH), 256, SMEM_TOTAL>>>();
    finalize_kernel<<<dim3(NTILE, BATCH), 128>>>(out);
}

// round 8
// speedup vs baseline: 11.0349x; 1.0779x over previous
#include <cuda_runtime.h>
#include <cuda_bf16.h>
#include <cuda_fp8.h>
#include <cstdint>
#include <math.h>

#define BATCH 8
#define SEQ   2048
#define DIM   512
#define BM    128
#define BN    128
#define NKP   4              // k-iterations (128 cols each)
#define NTILE (SEQ / BM)     // 16 row blocks
#define NBLK  (BATCH * NTILE)

#define SCALE8     50.59644256f      // 16 * sqrt(1/0.1)
#define INV256     0.00390625f
#define SHIFT      10.0f
#define LAMBDA     0.5f

// smem chunk: 64 fp8 cols, padded row stride 80 B (conflict-free ldmatrix)
#define RSTRIDE    80
#define CTILE_B    (BM * RSTRIDE)            // 10240 B per 64-col chunk
#define SM_A       0
#define SM_B       (8 * CTILE_B)             // 81920
#define SMEM_TOTAL (SM_B + 4 * CTILE_B)      // 122880 (B: 2 stages x 2 chunks)

__device__ uint8_t g_l8[BATCH * SEQ * DIM];          // 8 MB fp8 scratch
__device__ float g_rse[BATCH][NTILE][BM];            // row-side sumexp
__device__ float g_cse[BATCH][NTILE][8][BM];         // col-side sumexp
__device__ float g_cpart[BATCH][NTILE][DIM];         // column-sum partials (16a units)
__device__ float g_partials[NBLK];
__device__ int   g_cnt;

// ---------------------------------------------------------------------------
__device__ __forceinline__ uint32_t smem_u32(const void* p) {
    uint32_t a;
    asm("{ .reg .u64 t; cvta.to.shared.u64 t, %1; cvt.u32.u64 %0, t; }"
        : "=r"(a) : "l"(p));
    return a;
}
#define CP16(d, s) \
    asm volatile("cp.async.cg.shared.global [%0], [%1], 16;" :: "r"(d), "l"(s))
#define CP_COMMIT() asm volatile("cp.async.commit_group;" ::: "memory")
#define CP_WAIT(n)  asm volatile("cp.async.wait_group %0;" :: "n"(n) : "memory")

__device__ __forceinline__ void ldsm4(uint32_t* r, uint32_t addr) {
    asm volatile("ldmatrix.sync.aligned.m8n8.x4.shared.b16 {%0,%1,%2,%3}, [%4];"
                 : "=r"(r[0]), "=r"(r[1]), "=r"(r[2]), "=r"(r[3]) : "r"(addr));
}
__device__ __forceinline__ void mma16832(float* d, const uint32_t* a,
                                         uint32_t b0, uint32_t b1) {
    asm volatile(
        "mma.sync.aligned.m16n8k32.row.col.f32.e4m3.e4m3.f32 "
        "{%0,%1,%2,%3}, {%4,%5,%6,%7}, {%8,%9}, {%0,%1,%2,%3};"
        : "+f"(d[0]), "+f"(d[1]), "+f"(d[2]), "+f"(d[3])
        : "r"(a[0]), "r"(a[1]), "r"(a[2]), "r"(a[3]), "r"(b0), "r"(b1));
}
__device__ __forceinline__ float fp8_to_f32(uint8_t b) {
    __half_raw h = __nv_cvt_fp8_to_halfraw((__nv_fp8_storage_t)b, __NV_E4M3);
    return __half2float(*reinterpret_cast<__half*>(&h));
}

// ---------------------------------------------------------------------------
// Kernel 1: L2-normalize rows, fold 16*sqrt(1/T), emit e4m3.
// ---------------------------------------------------------------------------
__global__ void normalize_kernel(const float* __restrict__ x) {
    const int row = blockIdx.x;
    const int t   = threadIdx.x;                 // 0..127
    const float4 v = reinterpret_cast<const float4*>(x + (size_t)row * DIM)[t];
    float ss = fmaf(v.x, v.x, fmaf(v.y, v.y, fmaf(v.z, v.z, v.w * v.w)));
    #pragma unroll
    for (int o = 16; o > 0; o >>= 1) ss += __shfl_xor_sync(0xffffffffu, ss, o);
    __shared__ float ws[4];
    if ((t & 31) == 0) ws[t >> 5] = ss;
    __syncthreads();
    const float tot = ws[0] + ws[1] + ws[2] + ws[3];
    const float inv = SCALE8 / fmaxf(sqrtf(tot), 1e-8f);
    const __nv_fp8x2_storage_t p01 = __nv_cvt_float2_to_fp8x2(
        make_float2(v.x * inv, v.y * inv), __NV_SATFINITE, __NV_E4M3);
    const __nv_fp8x2_storage_t p23 = __nv_cvt_float2_to_fp8x2(
        make_float2(v.z * inv, v.w * inv), __NV_SATFINITE, __NV_E4M3);
    const uint32_t packed = (uint32_t)p01 | ((uint32_t)p23 << 16);
    reinterpret_cast<uint32_t*>(g_l8 + (size_t)row * DIM)[t] = packed;
}

// ---------------------------------------------------------------------------
// Kernel 2: symmetric e4m3 QMMA Gram GEMM + fused two-sided sumexp fold.
// CTA(i,b): row-block i resident; col-blocks j=(i+d)%16, d=0..(i<8?8:7).
// ---------------------------------------------------------------------------
__global__ void __launch_bounds__(256, 1) fused_mma_kernel() {
    extern __shared__ char smem[];
    const uint32_t sb  = smem_u32(smem);
    const int tid  = threadIdx.x;
    const int wid  = tid >> 5;
    const int lane = tid & 31;
    const int warp_m = wid >> 1;            // 0..3  (32 rows each)
    const int warp_n = wid & 1;             // 0..1  (64 cols each)
    const int bi = blockIdx.y;
    const int it = blockIdx.x;              // row block 0..15
    const int i0 = it * BM;
    const int njt = (it < 8) ? 9 : 8;

    const int g   = lane >> 2;              // row group 0..7
    const int tig = lane & 3;               // col pair 0..3

    const uint8_t* __restrict__ base = g_l8 + (size_t)bi * SEQ * DIM;
    const uint8_t* __restrict__ Ab   = base + (size_t)i0 * DIM;

    // ---- stage full A tile (128 x 512 fp8) into 8 chunk smem tiles ----
    #pragma unroll
    for (int u = 0; u < 16; ++u) {
        const int t = tid + u * 256;                  // 0..4095 (16B pieces)
        const int ch = t >> 9, rem = t & 511;
        const int r = rem >> 2, c = rem & 3;
        CP16(sb + SM_A + ch * CTILE_B + r * RSTRIDE + c * 16,
             Ab + (size_t)r * DIM + ch * 64 + c * 16);
    }
    CP_COMMIT();
    CP_WAIT(0);
    __syncthreads();

    // ---- column-sum partial of resident A rows (16a units) ----
    for (int col = tid; col < DIM; col += 256) {
        float s = 0.f;
        const uint32_t cb = (uint32_t)(col >> 6) * CTILE_B + (col & 63);
        #pragma unroll 8
        for (int r = 0; r < BM; ++r)
            s += fp8_to_f32(*reinterpret_cast<uint8_t*>(smem + cb + r * RSTRIDE));
        g_cpart[bi][it][col] = s;
    }

    // ldmatrix lane address components (rows lane&15, 16B sel lane>>4)
    const int lrow  = lane & 15;
    const int lsel  = (lane >> 4) & 1;

    float se[4];
    #pragma unroll
    for (int s = 0; s < 4; ++s) se[s] = 0.f;

    __shared__ float smc[8][64];            // col-side cross-warp stage
    __shared__ float se_red[8][8][4];       // row-side warp_n merge

    for (int m = 0; m < njt; ++m) {
        const int j = (it + m) & 15;
        const uint8_t* __restrict__ Bb = base + (size_t)(j * BN) * DIM;

        float acc[2][8][4];
        #pragma unroll
        for (int mt = 0; mt < 2; ++mt)
            #pragma unroll
            for (int nt = 0; nt < 8; ++nt)
                #pragma unroll
                for (int i = 0; i < 4; ++i) acc[mt][nt][i] = 0.f;

        // prologue: chunks 0,1 into stage 0
        {
            #pragma unroll
            for (int u = 0; u < 4; ++u) {
                const int t = tid + u * 256;          // 0..1023
                const int cc = t >> 9, rem = t & 511;
                const int r = rem >> 2, c = rem & 3;
                CP16(sb + SM_B + cc * CTILE_B + r * RSTRIDE + c * 16,
                     Bb + (size_t)r * DIM + cc * 64 + c * 16);
            }
            CP_COMMIT();
        }

        for (int kp = 0; kp < NKP; ++kp) {
            if (kp + 1 < NKP) {
                const uint32_t bdst = sb + SM_B + (((kp + 1) & 1) * 2) * CTILE_B;
                #pragma unroll
                for (int u = 0; u < 4; ++u) {
                    const int t = tid + u * 256;
                    const int cc = t >> 9, rem = t & 511;
                    const int r = rem >> 2, c = rem & 3;
                    CP16(bdst + cc * CTILE_B + r * RSTRIDE + c * 16,
                         Bb + (size_t)r * DIM + (kp + 1) * 128 + cc * 64 + c * 16);
                }
                CP_COMMIT();
                CP_WAIT(1);
            } else {
                CP_WAIT(0);
            }
            __syncthreads();

            #pragma unroll
            for (int cc = 0; cc < 2; ++cc) {
                const uint32_t abase = sb + SM_A + (kp * 2 + cc) * CTILE_B;
                const uint32_t bbase = sb + SM_B + ((kp & 1) * 2 + cc) * CTILE_B;
                #pragma unroll
                for (int ks = 0; ks < 2; ++ks) {
                    uint32_t af[2][4];
                    #pragma unroll
                    for (int mt = 0; mt < 2; ++mt)
                        ldsm4(af[mt], abase
                              + (warp_m * 32 + mt * 16 + lrow) * RSTRIDE
                              + ks * 32 + lsel * 16);
                    uint32_t bx[4][4];
                    #pragma unroll
                    for (int q = 0; q < 4; ++q)
                        ldsm4(bx[q], bbase
                              + (warp_n * 64 + q * 16 + lrow) * RSTRIDE
                              + ks * 32 + lsel * 16);
                    #pragma unroll
                    for (int mt = 0; mt < 2; ++mt)
                        #pragma unroll
                        for (int nt = 0; nt < 8; ++nt) {
                            const int q = nt >> 1, e = nt & 1;
                            mma16832(acc[mt][nt], af[mt], bx[q][e], bx[q][e + 2]);
                        }
                }
            }
            __syncthreads();
        }

        // ---- fused two-sided epilogue (sumexp only; v = acc/256) ----
        if (m == 0) {
            #pragma unroll
            for (int mt = 0; mt < 2; ++mt)
                #pragma unroll
                for (int nt = 0; nt < 8; ++nt)
                    #pragma unroll
                    for (int i = 0; i < 4; ++i) {
                        const int lr = warp_m * 32 + mt * 16 + (i >> 1) * 8 + g;
                        const int lc = warp_n * 64 + nt * 8 + tig * 2 + (i & 1);
                        if (lr != lc)
                            se[mt * 2 + (i >> 1)] +=
                                __expf(fmaf(acc[mt][nt][i], INV256, -SHIFT));
                    }
        } else {
            float cse[16];
            #pragma unroll
            for (int q = 0; q < 16; ++q) cse[q] = 0.f;
            #pragma unroll
            for (int mt = 0; mt < 2; ++mt)
                #pragma unroll
                for (int nt = 0; nt < 8; ++nt)
                    #pragma unroll
                    for (int i = 0; i < 4; ++i) {
                        const float e =
                            __expf(fmaf(acc[mt][nt][i], INV256, -SHIFT));
                        se[mt * 2 + (i >> 1)] += e;
                        cse[nt * 2 + (i & 1)] += e;
                    }
            #pragma unroll
            for (int q = 0; q < 16; ++q) {
                #pragma unroll
                for (int o = 4; o < 32; o <<= 1)
                    cse[q] += __shfl_xor_sync(0xffffffffu, cse[q], o);
            }
            if (lane < 4) {      // lane == tig, g == 0
                #pragma unroll
                for (int nt = 0; nt < 8; ++nt)
                    #pragma unroll
                    for (int b2 = 0; b2 < 2; ++b2)
                        smc[wid][nt * 8 + lane * 2 + b2] = cse[nt * 2 + b2];
            }
            __syncthreads();
            if (tid < BM) {      // combine warp_m quadrants, single-writer STG
                const int wn = tid >> 6, lc = tid & 63;
                float cs = 0.f;
                #pragma unroll
                for (int wm = 0; wm < 4; ++wm)
                    cs += smc[wm * 2 + wn][lc];
                g_cse[bi][j][m - 1][tid] = cs;
            }
            __syncthreads();     // protect smc for next tile
        }
    }

    // ---- row-side: quad reduce, merge warp_n halves, store partials ----
    #pragma unroll
    for (int s = 0; s < 4; ++s) {
        #pragma unroll
        for (int o = 1; o < 4; o <<= 1)
            se[s] += __shfl_xor_sync(0xffffffffu, se[s], o);
    }
    if (tig == 0) {
        #pragma unroll
        for (int s = 0; s < 4; ++s) se_red[wid][g][s] = se[s];
    }
    __syncthreads();
    if (tid < BM) {
        const int wm = tid >> 5;
        const int gg = (tid >> 2) & 7;
        const int ss = tid & 3;
        const int row = wm * 32 + (ss >> 1) * 16 + (ss & 1) * 8 + gg;
        g_rse[bi][it][row] = se_red[wm * 2][gg][ss] + se_red[wm * 2 + 1][gg][ss];
    }
}

// ---------------------------------------------------------------------------
// Kernel 3: merged finalize — batch colsum vector, per-row seT + analytic
// rowsum (dot/256 - 10), log, block partial, counter-elected final reduce.
// ---------------------------------------------------------------------------
__global__ void finalize_kernel(float* __restrict__ out) {
    const int k = blockIdx.x;       // row block
    const int b = blockIdx.y;
    const int r = threadIdx.x;      // 0..127

    __shared__ float c[DIM];
    __shared__ float ws[4];
    __shared__ int   flag;

    for (int comp = r; comp < DIM; comp += 128) {
        float s = 0.f;
        #pragma unroll
        for (int p = 0; p < NTILE; ++p) s += g_cpart[b][p][comp];
        c[comp] = s;
    }
    __syncthreads();

    float seT = g_rse[b][k][r];
    const int nslots = (k >= 8) ? 8 : 7;
    for (int d = 0; d < nslots; ++d) seT += g_cse[b][k][d][r];

    // analytic rowsum: <16a_row, c>/256 - SHIFT
    const uint4* __restrict__ a4 = reinterpret_cast<const uint4*>(
        g_l8 + ((size_t)b * SEQ + (size_t)k * BM + r) * DIM);
    float dot = 0.f;
    #pragma unroll 4
    for (int qi = 0; qi < DIM / 16; ++qi) {
        const uint4 u = __ldg(a4 + qi);
        const uint32_t w[4] = {u.x, u.y, u.z, u.w};
        #pragma unroll
        for (int wi = 0; wi < 4; ++wi) {
            const __half2_raw h0 = __nv_cvt_fp8x2_to_halfraw2(
                (__nv_fp8x2_storage_t)(w[wi] & 0xffffu), __NV_E4M3);
            const __half2_raw h1 = __nv_cvt_fp8x2_to_halfraw2(
                (__nv_fp8x2_storage_t)(w[wi] >> 16), __NV_E4M3);
            const float2 f0 = __half22float2(*reinterpret_cast<const __half2*>(&h0));
            const float2 f1 = __half22float2(*reinterpret_cast<const __half2*>(&h1));
            const float* cb = c + qi * 16 + wi * 4;
            dot = fmaf(f0.x, cb[0], dot);
            dot = fmaf(f0.y, cb[1], dot);
            dot = fmaf(f1.x, cb[2], dot);
            dot = fmaf(f1.y, cb[3], dot);
        }
    }

    float contrib = (float)(SEQ - 1) * (SHIFT + logf(seT))
                  - (fmaf(dot, INV256, -SHIFT));
    #pragma unroll
    for (int o = 16; o > 0; o >>= 1)
        contrib += __shfl_xor_sync(0xffffffffu, contrib, o);
    if ((r & 31) == 0) ws[r >> 5] = contrib;
    __syncthreads();
    if (r == 0) {
        g_partials[b * NTILE + k] = ws[0] + ws[1] + ws[2] + ws[3];
        __threadfence();
        const int t = atomicAdd(&g_cnt, 1);
        flag = (t == NBLK - 1) ? 1 : 0;
    }
    __syncthreads();

    if (flag) {
        __threadfence();
        float v = __ldcg(&g_partials[r]);
        #pragma unroll
        for (int o = 16; o > 0; o >>= 1)
            v += __shfl_xor_sync(0xffffffffu, v, o);
        if ((r & 31) == 0) ws[r >> 5] = v;
        __syncthreads();
        if (r == 0) {
            const float total = ws[0] + ws[1] + ws[2] + ws[3];
            out[0] = total * (LAMBDA / ((float)BATCH * (float)SEQ * (float)SEQ));
            g_cnt = 0;               // reset for next graph replay
        }
    }
}

extern "C" void kernel_launch(void* const* d_in, const int* in_sizes, int n_in,
                              void* d_out, int out_size) {
    (void)in_sizes; (void)n_in; (void)out_size;
    const float* x = (const float*)d_in[0];
    float* out = (float*)d_out;

    cudaFuncSetAttribute(fused_mma_kernel,
                         cudaFuncAttributeMaxDynamicSharedMemorySize, SMEM_TOTAL);

    normalize_kernel<<<BATCH * SEQ, 128>>>(x);
    fused_mma_kernel<<<dim3(NTILE, BATCH), 256, SMEM_TOTAL>>>();
    finalize_kernel<<<dim3(NTILE, BATCH), 128>>>(out);
}

// round 9
// speedup vs baseline: 11.6986x; 1.0601x over previous
#include <cuda_runtime.h>
#include <cuda_bf16.h>
#include <cuda_fp8.h>
#include <cstdint>
#include <math.h>

#define BATCH 8
#define SEQ   2048
#define DIM   512
#define BM    128
#define BN    128
#define NKP   4              // k-iterations (128 cols each)
#define NTILE (SEQ / BM)     // 16 row blocks
#define NBLK  (BATCH * NTILE)
#define NJOBS 136            // 8*9 + 8*8 tile jobs per batch

#define SCALE8     50.59644256f      // 16 * sqrt(1/0.1)
#define INV256     0.00390625f
#define SHIFT      10.0f
#define LAMBDA     0.5f

// smem chunk: 64 fp8 cols, padded row stride 80 B (conflict-free ldmatrix)
#define RSTRIDE    80
#define CTILE_B    (BM * RSTRIDE)            // 10240 B per 64-col chunk
// 2 stages x (2 A-chunks + 2 B-chunks)
#define SMEM_TOTAL (8 * CTILE_B)             // 81920

__device__ uint8_t g_l8[BATCH * SEQ * DIM];          // 8 MB fp8 scratch
__device__ float g_rse[BATCH][NTILE][9][BM];         // row-side sumexp slots
__device__ float g_cse[BATCH][NTILE][8][BM];         // col-side sumexp slots
__device__ float g_cpart[BATCH][NTILE][DIM];         // column-sum partials
__device__ float g_partials[NBLK];
__device__ int   g_cnt;

// ---------------------------------------------------------------------------
__device__ __forceinline__ uint32_t smem_u32(const void* p) {
    uint32_t a;
    asm("{ .reg .u64 t; cvta.to.shared.u64 t, %1; cvt.u32.u64 %0, t; }"
        : "=r"(a) : "l"(p));
    return a;
}
#define CP16(d, s) \
    asm volatile("cp.async.cg.shared.global [%0], [%1], 16;" :: "r"(d), "l"(s))
#define CP_COMMIT() asm volatile("cp.async.commit_group;" ::: "memory")
#define CP_WAIT(n)  asm volatile("cp.async.wait_group %0;" :: "n"(n) : "memory")

__device__ __forceinline__ void ldsm4(uint32_t* r, uint32_t addr) {
    asm volatile("ldmatrix.sync.aligned.m8n8.x4.shared.b16 {%0,%1,%2,%3}, [%4];"
                 : "=r"(r[0]), "=r"(r[1]), "=r"(r[2]), "=r"(r[3]) : "r"(addr));
}
__device__ __forceinline__ void mma16832(float* d, const uint32_t* a,
                                         uint32_t b0, uint32_t b1) {
    asm volatile(
        "mma.sync.aligned.m16n8k32.row.col.f32.e4m3.e4m3.f32 "
        "{%0,%1,%2,%3}, {%4,%5,%6,%7}, {%8,%9}, {%0,%1,%2,%3};"
        : "+f"(d[0]), "+f"(d[1]), "+f"(d[2]), "+f"(d[3])
        : "r"(a[0]), "r"(a[1]), "r"(a[2]), "r"(a[3]), "r"(b0), "r"(b1));
}
__device__ __forceinline__ float2 fp8x2_to_f2(uint16_t v) {
    const __half2_raw h = __nv_cvt_fp8x2_to_halfraw2((__nv_fp8x2_storage_t)v,
                                                     __NV_E4M3);
    return __half22float2(*reinterpret_cast<const __half2*>(&h));
}

// ---------------------------------------------------------------------------
// Kernel 1: warp-per-row L2-normalize, fold 16*sqrt(1/T), emit e4m3.
// Barrier-free: 8 warps/block, one row each.
// ---------------------------------------------------------------------------
__global__ void normalize_kernel(const float* __restrict__ x) {
    const int wid  = threadIdx.x >> 5;
    const int lane = threadIdx.x & 31;
    const int row  = blockIdx.x * 8 + wid;
    const float4* __restrict__ xr =
        reinterpret_cast<const float4*>(x + (size_t)row * DIM) + lane * 4;
    float4 v[4];
    float ss = 0.f;
    #pragma unroll
    for (int q = 0; q < 4; ++q) {
        v[q] = xr[q];
        ss = fmaf(v[q].x, v[q].x, ss);
        ss = fmaf(v[q].y, v[q].y, ss);
        ss = fmaf(v[q].z, v[q].z, ss);
        ss = fmaf(v[q].w, v[q].w, ss);
    }
    #pragma unroll
    for (int o = 16; o > 0; o >>= 1) ss += __shfl_xor_sync(0xffffffffu, ss, o);
    const float inv = SCALE8 / fmaxf(sqrtf(ss), 1e-8f);
    uint32_t w[4];
    #pragma unroll
    for (int q = 0; q < 4; ++q) {
        const __nv_fp8x2_storage_t p01 = __nv_cvt_float2_to_fp8x2(
            make_float2(v[q].x * inv, v[q].y * inv), __NV_SATFINITE, __NV_E4M3);
        const __nv_fp8x2_storage_t p23 = __nv_cvt_float2_to_fp8x2(
            make_float2(v[q].z * inv, v[q].w * inv), __NV_SATFINITE, __NV_E4M3);
        w[q] = (uint32_t)p01 | ((uint32_t)p23 << 16);
    }
    uint4 o4;
    o4.x = w[0]; o4.y = w[1]; o4.z = w[2]; o4.w = w[3];
    *reinterpret_cast<uint4*>(g_l8 + (size_t)row * DIM + lane * 16) = o4;
}

// ---------------------------------------------------------------------------
// Kernel 2: per-row-block column sums (for analytic rowsum).
// ---------------------------------------------------------------------------
__global__ void colsum_kernel() {
    const int k = blockIdx.x, b = blockIdx.y;
    const int t = threadIdx.x;              // 0..127 -> cols 4t..4t+3
    const uint32_t* __restrict__ p = reinterpret_cast<const uint32_t*>(
        g_l8 + ((size_t)b * SEQ + (size_t)k * BM) * DIM) + t;
    float s0 = 0.f, s1 = 0.f, s2 = 0.f, s3 = 0.f;
    #pragma unroll 8
    for (int r = 0; r < BM; ++r) {
        const uint32_t w = __ldg(p + r * (DIM / 4));
        const float2 f0 = fp8x2_to_f2((uint16_t)(w & 0xffffu));
        const float2 f1 = fp8x2_to_f2((uint16_t)(w >> 16));
        s0 += f0.x; s1 += f0.y; s2 += f1.x; s3 += f1.y;
    }
    float4 o;
    o.x = s0; o.y = s1; o.z = s2; o.w = s3;
    *reinterpret_cast<float4*>(&g_cpart[b][k][t * 4]) = o;
}

// ---------------------------------------------------------------------------
// Kernel 3: one 128x128 tile job per CTA. 1088 CTAs, 2 CTAs/SM.
// Job -> (row block it, offset m); col block j = (it+m)%16.
// Streams A and B chunk pairs per k-iter, double-buffered.
// ---------------------------------------------------------------------------
__global__ void __launch_bounds__(256, 2) fused_mma_kernel() {
    extern __shared__ char smem[];
    const uint32_t sb  = smem_u32(smem);
    const int tid  = threadIdx.x;
    const int wid  = tid >> 5;
    const int lane = tid & 31;
    const int warp_m = wid >> 1;            // 0..3  (32 rows each)
    const int warp_n = wid & 1;             // 0..1  (64 cols each)
    const int bi = blockIdx.y;

    int it, m;
    if (blockIdx.x < 72) { it = blockIdx.x / 9; m = blockIdx.x % 9; }
    else { const int t2 = blockIdx.x - 72; it = 8 + t2 / 8; m = t2 % 8; }
    const int j = (it + m) & 15;

    const int g   = lane >> 2;              // row group 0..7
    const int tig = lane & 3;               // col pair 0..3

    const uint8_t* __restrict__ base = g_l8 + (size_t)bi * SEQ * DIM;
    const uint8_t* __restrict__ Ab   = base + (size_t)(it * BM) * DIM;
    const uint8_t* __restrict__ Bb   = base + (size_t)(j * BN) * DIM;

    // stage loader: 4 chunks (A0,A1,B0,B1) = 2048 x 16B pieces, 8 per thread
    auto load_stage = [&](int stage, int kp) {
        const uint32_t sbase = sb + stage * 4 * CTILE_B;
        #pragma unroll
        for (int u = 0; u < 8; ++u) {
            const int p  = tid + u * 256;           // 0..2047
            const int ch = p >> 9;                  // 0..3
            const int rem = p & 511;
            const int r = rem >> 2, c = rem & 3;
            const uint8_t* src = (ch < 2 ? Ab : Bb)
                + (size_t)r * DIM + kp * 128 + (ch & 1) * 64 + c * 16;
            CP16(sbase + ch * CTILE_B + r * RSTRIDE + c * 16, src);
        }
        CP_COMMIT();
    };

    load_stage(0, 0);

    const int lrow = lane & 15;
    const int lsel = (lane >> 4) & 1;

    float acc[2][8][4];
    #pragma unroll
    for (int mt = 0; mt < 2; ++mt)
        #pragma unroll
        for (int nt = 0; nt < 8; ++nt)
            #pragma unroll
            for (int i = 0; i < 4; ++i) acc[mt][nt][i] = 0.f;

    for (int kp = 0; kp < NKP; ++kp) {
        if (kp + 1 < NKP) {
            load_stage((kp + 1) & 1, kp + 1);
            CP_WAIT(1);
        } else {
            CP_WAIT(0);
        }
        __syncthreads();

        #pragma unroll
        for (int cc = 0; cc < 2; ++cc) {
            const uint32_t abase = sb + ((kp & 1) * 4 + cc) * CTILE_B;
            const uint32_t bbase = sb + ((kp & 1) * 4 + 2 + cc) * CTILE_B;
            #pragma unroll
            for (int ks = 0; ks < 2; ++ks) {
                uint32_t af[2][4];
                #pragma unroll
                for (int mt = 0; mt < 2; ++mt)
                    ldsm4(af[mt], abase
                          + (warp_m * 32 + mt * 16 + lrow) * RSTRIDE
                          + ks * 32 + lsel * 16);
                uint32_t bx[4][4];
                #pragma unroll
                for (int q = 0; q < 4; ++q)
                    ldsm4(bx[q], bbase
                          + (warp_n * 64 + q * 16 + lrow) * RSTRIDE
                          + ks * 32 + lsel * 16);
                #pragma unroll
                for (int mt = 0; mt < 2; ++mt)
                    #pragma unroll
                    for (int nt = 0; nt < 8; ++nt) {
                        const int q = nt >> 1, e = nt & 1;
                        mma16832(acc[mt][nt], af[mt], bx[q][e], bx[q][e + 2]);
                    }
            }
        }
        __syncthreads();
    }

    // ---- fused two-sided epilogue (sumexp only; v = acc/256) ----
    __shared__ float smc[8][64];
    __shared__ float se_red[8][8][4];

    float se[4];
    #pragma unroll
    for (int s = 0; s < 4; ++s) se[s] = 0.f;

    if (m == 0) {
        #pragma unroll
        for (int mt = 0; mt < 2; ++mt)
            #pragma unroll
            for (int nt = 0; nt < 8; ++nt)
                #pragma unroll
                for (int i = 0; i < 4; ++i) {
                    const int lr = warp_m * 32 + mt * 16 + (i >> 1) * 8 + g;
                    const int lc = warp_n * 64 + nt * 8 + tig * 2 + (i & 1);
                    if (lr != lc)
                        se[mt * 2 + (i >> 1)] +=
                            __expf(fmaf(acc[mt][nt][i], INV256, -SHIFT));
                }
    } else {
        float cse[16];
        #pragma unroll
        for (int q = 0; q < 16; ++q) cse[q] = 0.f;
        #pragma unroll
        for (int mt = 0; mt < 2; ++mt)
            #pragma unroll
            for (int nt = 0; nt < 8; ++nt)
                #pragma unroll
                for (int i = 0; i < 4; ++i) {
                    const float e = __expf(fmaf(acc[mt][nt][i], INV256, -SHIFT));
                    se[mt * 2 + (i >> 1)] += e;
                    cse[nt * 2 + (i & 1)] += e;
                }
        #pragma unroll
        for (int q = 0; q < 16; ++q) {
            #pragma unroll
            for (int o = 4; o < 32; o <<= 1)
                cse[q] += __shfl_xor_sync(0xffffffffu, cse[q], o);
        }
        if (lane < 4) {          // lane == tig, g == 0
            #pragma unroll
            for (int nt = 0; nt < 8; ++nt)
                #pragma unroll
                for (int b2 = 0; b2 < 2; ++b2)
                    smc[wid][nt * 8 + lane * 2 + b2] = cse[nt * 2 + b2];
        }
    }

    // row-side quad reduce + stage
    #pragma unroll
    for (int s = 0; s < 4; ++s) {
        #pragma unroll
        for (int o = 1; o < 4; o <<= 1)
            se[s] += __shfl_xor_sync(0xffffffffu, se[s], o);
    }
    if (tig == 0) {
        #pragma unroll
        for (int s = 0; s < 4; ++s) se_red[wid][g][s] = se[s];
    }
    __syncthreads();

    if (tid < BM) {
        // row-side: merge warp_n halves, write slot m
        const int wm = tid >> 5;
        const int gg = (tid >> 2) & 7;
        const int ss = tid & 3;
        const int row = wm * 32 + (ss >> 1) * 16 + (ss & 1) * 8 + gg;
        g_rse[bi][it][m][row] =
            se_red[wm * 2][gg][ss] + se_red[wm * 2 + 1][gg][ss];
    } else if (m > 0) {
        // col-side: combine warp_m quadrants, write slot m-1
        const int t2 = tid - BM;             // 0..127
        const int wn = t2 >> 6, lc = t2 & 63;
        float cs = 0.f;
        #pragma unroll
        for (int wm = 0; wm < 4; ++wm) cs += smc[wm * 2 + wn][lc];
        g_cse[bi][j][m - 1][t2] = cs;
    }
}

// ---------------------------------------------------------------------------
// Kernel 4: finalize — batch colsum vector, per-row seT (row+col slots) +
// analytic rowsum, log, block partial, counter-elected final reduce.
// ---------------------------------------------------------------------------
__global__ void finalize_kernel(float* __restrict__ out) {
    const int k = blockIdx.x;
    const int b = blockIdx.y;
    const int r = threadIdx.x;              // 0..127

    __shared__ float c[DIM];
    __shared__ float ws[4];
    __shared__ int   flag;

    for (int comp = r; comp < DIM; comp += 128) {
        float s = 0.f;
        #pragma unroll
        for (int p = 0; p < NTILE; ++p) s += g_cpart[b][p][comp];
        c[comp] = s;
    }
    __syncthreads();

    const int nrow = (k < 8) ? 9 : 8;
    const int ncol = (k >= 8) ? 8 : 7;
    float seT = 0.f;
    for (int d = 0; d < nrow; ++d) seT += g_rse[b][k][d][r];
    for (int d = 0; d < ncol; ++d) seT += g_cse[b][k][d][r];

    // analytic rowsum: <16a_row, c>/256 - SHIFT
    const uint4* __restrict__ a4 = reinterpret_cast<const uint4*>(
        g_l8 + ((size_t)b * SEQ + (size_t)k * BM + r) * DIM);
    float dot = 0.f;
    #pragma unroll 4
    for (int qi = 0; qi < DIM / 16; ++qi) {
        const uint4 u = __ldg(a4 + qi);
        const uint32_t w[4] = {u.x, u.y, u.z, u.w};
        #pragma unroll
        for (int wi = 0; wi < 4; ++wi) {
            const float2 f0 = fp8x2_to_f2((uint16_t)(w[wi] & 0xffffu));
            const float2 f1 = fp8x2_to_f2((uint16_t)(w[wi] >> 16));
            const float* cb = c + qi * 16 + wi * 4;
            dot = fmaf(f0.x, cb[0], dot);
            dot = fmaf(f0.y, cb[1], dot);
            dot = fmaf(f1.x, cb[2], dot);
            dot = fmaf(f1.y, cb[3], dot);
        }
    }

    float contrib = (float)(SEQ - 1) * (SHIFT + logf(seT))
                  - (fmaf(dot, INV256, -SHIFT));
    #pragma unroll
    for (int o = 16; o > 0; o >>= 1)
        contrib += __shfl_xor_sync(0xffffffffu, contrib, o);
    if ((r & 31) == 0) ws[r >> 5] = contrib;
    __syncthreads();
    if (r == 0) {
        g_partials[b * NTILE + k] = ws[0] + ws[1] + ws[2] + ws[3];
        __threadfence();
        const int t = atomicAdd(&g_cnt, 1);
        flag = (t == NBLK - 1) ? 1 : 0;
    }
    __syncthreads();

    if (flag) {
        __threadfence();
        float v = __ldcg(&g_partials[r]);
        #pragma unroll
        for (int o = 16; o > 0; o >>= 1)
            v += __shfl_xor_sync(0xffffffffu, v, o);
        if ((r & 31) == 0) ws[r >> 5] = v;
        __syncthreads();
        if (r == 0) {
            const float total = ws[0] + ws[1] + ws[2] + ws[3];
            out[0] = total * (LAMBDA / ((float)BATCH * (float)SEQ * (float)SEQ));
            g_cnt = 0;               // reset for next graph replay
        }
    }
}

extern "C" void kernel_launch(void* const* d_in, const int* in_sizes, int n_in,
                              void* d_out, int out_size) {
    (void)in_sizes; (void)n_in; (void)out_size;
    const float* x = (const float*)d_in[0];
    float* out = (float*)d_out;

    cudaFuncSetAttribute(fused_mma_kernel,
                         cudaFuncAttributeMaxDynamicSharedMemorySize, SMEM_TOTAL);

    normalize_kernel<<<SEQ * BATCH / 8, 256>>>(x);
    colsum_kernel<<<dim3(NTILE, BATCH), 128>>>();
    fused_mma_kernel<<<dim3(NJOBS, BATCH), 256, SMEM_TOTAL>>>();
    finalize_kernel<<<dim3(NTILE, BATCH), 128>>>(out);
}

// round 10
// speedup vs baseline: 11.9112x; 1.0182x over previous
#include <cuda_runtime.h>
#include <cuda_bf16.h>
#include <cuda_fp8.h>
#include <cstdint>
#include <math.h>

#define BATCH 8
#define SEQ   2048
#define DIM   512
#define BM    128
#define BN    128
#define NKP   4              // k-iterations (128 cols each)
#define NTILE (SEQ / BM)     // 16 row blocks
#define NBLK  (BATCH * NTILE)
#define NJOBS 136            // 8*9 + 8*8 tile jobs per batch

#define SCALE8     50.59644256f      // 16 * sqrt(1/0.1)
#define INV256     0.00390625f
#define SHIFT      10.0f
#define LAMBDA     0.5f

// smem chunk: 64 fp8 cols, padded row stride 80 B (conflict-free ldmatrix)
#define RSTRIDE    80
#define CTILE_B    (BM * RSTRIDE)            // 10240 B per 64-col chunk
// 2 stages x (2 A-chunks + 2 B-chunks)
#define SMEM_TOTAL (8 * CTILE_B)             // 81920

__device__ uint8_t g_l8[BATCH * SEQ * DIM];          // 8 MB fp8 scratch
__device__ float g_rse[BATCH][NTILE][9][BM];         // row-side sumexp slots
__device__ float g_cse[BATCH][NTILE][8][BM];         // col-side sumexp slots
__device__ float g_cpart[BATCH][NTILE * 2][DIM];     // half-block column sums
__device__ float g_partials[NBLK];
__device__ int   g_cnt;

// ---------------------------------------------------------------------------
__device__ __forceinline__ uint32_t smem_u32(const void* p) {
    uint32_t a;
    asm("{ .reg .u64 t; cvta.to.shared.u64 t, %1; cvt.u32.u64 %0, t; }"
        : "=r"(a) : "l"(p));
    return a;
}
#define CP16(d, s) \
    asm volatile("cp.async.cg.shared.global [%0], [%1], 16;" :: "r"(d), "l"(s))
#define CP_COMMIT() asm volatile("cp.async.commit_group;" ::: "memory")
#define CP_WAIT(n)  asm volatile("cp.async.wait_group %0;" :: "n"(n) : "memory")

__device__ __forceinline__ void ldsm4(uint32_t* r, uint32_t addr) {
    asm volatile("ldmatrix.sync.aligned.m8n8.x4.shared.b16 {%0,%1,%2,%3}, [%4];"
                 : "=r"(r[0]), "=r"(r[1]), "=r"(r[2]), "=r"(r[3]) : "r"(addr));
}
__device__ __forceinline__ void mma16832(float* d, const uint32_t* a,
                                         uint32_t b0, uint32_t b1) {
    asm volatile(
        "mma.sync.aligned.m16n8k32.row.col.f32.e4m3.e4m3.f32 "
        "{%0,%1,%2,%3}, {%4,%5,%6,%7}, {%8,%9}, {%0,%1,%2,%3};"
        : "+f"(d[0]), "+f"(d[1]), "+f"(d[2]), "+f"(d[3])
        : "r"(a[0]), "r"(a[1]), "r"(a[2]), "r"(a[3]), "r"(b0), "r"(b1));
}
__device__ __forceinline__ float2 fp8x2_to_f2(uint16_t v) {
    const __half2_raw h = __nv_cvt_fp8x2_to_halfraw2((__nv_fp8x2_storage_t)v,
                                                     __NV_E4M3);
    return __half22float2(*reinterpret_cast<const __half2*>(&h));
}

// ---------------------------------------------------------------------------
// Kernel 1: warp-per-row L2-normalize, fold 16*sqrt(1/T), emit e4m3.
// ---------------------------------------------------------------------------
__global__ void normalize_kernel(const float* __restrict__ x) {
    const int wid  = threadIdx.x >> 5;
    const int lane = threadIdx.x & 31;
    const int row  = blockIdx.x * 8 + wid;
    const float4* __restrict__ xr =
        reinterpret_cast<const float4*>(x + (size_t)row * DIM) + lane * 4;
    float4 v[4];
    float ss = 0.f;
    #pragma unroll
    for (int q = 0; q < 4; ++q) {
        v[q] = xr[q];
        ss = fmaf(v[q].x, v[q].x, ss);
        ss = fmaf(v[q].y, v[q].y, ss);
        ss = fmaf(v[q].z, v[q].z, ss);
        ss = fmaf(v[q].w, v[q].w, ss);
    }
    #pragma unroll
    for (int o = 16; o > 0; o >>= 1) ss += __shfl_xor_sync(0xffffffffu, ss, o);
    const float inv = SCALE8 / fmaxf(sqrtf(ss), 1e-8f);
    uint32_t w[4];
    #pragma unroll
    for (int q = 0; q < 4; ++q) {
        const __nv_fp8x2_storage_t p01 = __nv_cvt_float2_to_fp8x2(
            make_float2(v[q].x * inv, v[q].y * inv), __NV_SATFINITE, __NV_E4M3);
        const __nv_fp8x2_storage_t p23 = __nv_cvt_float2_to_fp8x2(
            make_float2(v[q].z * inv, v[q].w * inv), __NV_SATFINITE, __NV_E4M3);
        w[q] = (uint32_t)p01 | ((uint32_t)p23 << 16);
    }
    uint4 o4;
    o4.x = w[0]; o4.y = w[1]; o4.z = w[2]; o4.w = w[3];
    *reinterpret_cast<uint4*>(g_l8 + (size_t)row * DIM + lane * 16) = o4;
}

// ---------------------------------------------------------------------------
// Kernel 2: half-block (64-row) column sums for the analytic rowsum.
// ---------------------------------------------------------------------------
__global__ void colsum_kernel() {
    const int kh = blockIdx.x;              // half-block 0..31
    const int b  = blockIdx.y;
    const int t  = threadIdx.x;             // 0..127 -> cols 4t..4t+3
    const uint32_t* __restrict__ p = reinterpret_cast<const uint32_t*>(
        g_l8 + ((size_t)b * SEQ + (size_t)kh * 64) * DIM) + t;
    float s0 = 0.f, s1 = 0.f, s2 = 0.f, s3 = 0.f;
    #pragma unroll 8
    for (int r = 0; r < 64; ++r) {
        const uint32_t w = __ldg(p + r * (DIM / 4));
        const float2 f0 = fp8x2_to_f2((uint16_t)(w & 0xffffu));
        const float2 f1 = fp8x2_to_f2((uint16_t)(w >> 16));
        s0 += f0.x; s1 += f0.y; s2 += f1.x; s3 += f1.y;
    }
    float4 o;
    o.x = s0; o.y = s1; o.z = s2; o.w = s3;
    *reinterpret_cast<float4*>(&g_cpart[b][kh][t * 4]) = o;
}

// ---------------------------------------------------------------------------
// Kernel 3: one 128x128 tile job per CTA. 1088 CTAs, 2 CTAs/SM.
// ---------------------------------------------------------------------------
__global__ void __launch_bounds__(256, 2) fused_mma_kernel() {
    extern __shared__ char smem[];
    const uint32_t sb  = smem_u32(smem);
    const int tid  = threadIdx.x;
    const int wid  = tid >> 5;
    const int lane = tid & 31;
    const int warp_m = wid >> 1;            // 0..3  (32 rows each)
    const int warp_n = wid & 1;             // 0..1  (64 cols each)
    const int bi = blockIdx.y;

    int it, m;
    if (blockIdx.x < 72) { it = blockIdx.x / 9; m = blockIdx.x % 9; }
    else { const int t2 = blockIdx.x - 72; it = 8 + t2 / 8; m = t2 % 8; }
    const int j = (it + m) & 15;

    const int g   = lane >> 2;              // row group 0..7
    const int tig = lane & 3;               // col pair 0..3

    const uint8_t* __restrict__ base = g_l8 + (size_t)bi * SEQ * DIM;
    const uint8_t* __restrict__ Ab   = base + (size_t)(it * BM) * DIM;
    const uint8_t* __restrict__ Bb   = base + (size_t)(j * BN) * DIM;

    auto load_stage = [&](int stage, int kp) {
        const uint32_t sbase = sb + stage * 4 * CTILE_B;
        #pragma unroll
        for (int u = 0; u < 8; ++u) {
            const int p  = tid + u * 256;           // 0..2047
            const int ch = p >> 9;                  // 0..3
            const int rem = p & 511;
            const int r = rem >> 2, c = rem & 3;
            const uint8_t* src = (ch < 2 ? Ab : Bb)
                + (size_t)r * DIM + kp * 128 + (ch & 1) * 64 + c * 16;
            CP16(sbase + ch * CTILE_B + r * RSTRIDE + c * 16, src);
        }
        CP_COMMIT();
    };

    load_stage(0, 0);

    const int lrow = lane & 15;
    const int lsel = (lane >> 4) & 1;

    float acc[2][8][4];
    #pragma unroll
    for (int mt = 0; mt < 2; ++mt)
        #pragma unroll
        for (int nt = 0; nt < 8; ++nt)
            #pragma unroll
            for (int i = 0; i < 4; ++i) acc[mt][nt][i] = 0.f;

    for (int kp = 0; kp < NKP; ++kp) {
        if (kp + 1 < NKP) {
            load_stage((kp + 1) & 1, kp + 1);
            CP_WAIT(1);
        } else {
            CP_WAIT(0);
        }
        __syncthreads();

        #pragma unroll
        for (int cc = 0; cc < 2; ++cc) {
            const uint32_t abase = sb + ((kp & 1) * 4 + cc) * CTILE_B;
            const uint32_t bbase = sb + ((kp & 1) * 4 + 2 + cc) * CTILE_B;
            #pragma unroll
            for (int ks = 0; ks < 2; ++ks) {
                uint32_t af[2][4];
                #pragma unroll
                for (int mt = 0; mt < 2; ++mt)
                    ldsm4(af[mt], abase
                          + (warp_m * 32 + mt * 16 + lrow) * RSTRIDE
                          + ks * 32 + lsel * 16);
                uint32_t bx[4][4];
                #pragma unroll
                for (int q = 0; q < 4; ++q)
                    ldsm4(bx[q], bbase
                          + (warp_n * 64 + q * 16 + lrow) * RSTRIDE
                          + ks * 32 + lsel * 16);
                #pragma unroll
                for (int mt = 0; mt < 2; ++mt)
                    #pragma unroll
                    for (int nt = 0; nt < 8; ++nt) {
                        const int q = nt >> 1, e = nt & 1;
                        mma16832(acc[mt][nt], af[mt], bx[q][e], bx[q][e + 2]);
                    }
            }
        }
        __syncthreads();
    }

    // ---- fused two-sided epilogue (sumexp only; v = acc/256) ----
    __shared__ float smc[8][64];
    __shared__ float se_red[8][8][4];

    float se[4];
    #pragma unroll
    for (int s = 0; s < 4; ++s) se[s] = 0.f;

    if (m == 0) {
        #pragma unroll
        for (int mt = 0; mt < 2; ++mt)
            #pragma unroll
            for (int nt = 0; nt < 8; ++nt)
                #pragma unroll
                for (int i = 0; i < 4; ++i) {
                    const int lr = warp_m * 32 + mt * 16 + (i >> 1) * 8 + g;
                    const int lc = warp_n * 64 + nt * 8 + tig * 2 + (i & 1);
                    if (lr != lc)
                        se[mt * 2 + (i >> 1)] +=
                            __expf(fmaf(acc[mt][nt][i], INV256, -SHIFT));
                }
    } else {
        float cse[16];
        #pragma unroll
        for (int q = 0; q < 16; ++q) cse[q] = 0.f;
        #pragma unroll
        for (int mt = 0; mt < 2; ++mt)
            #pragma unroll
            for (int nt = 0; nt < 8; ++nt)
                #pragma unroll
                for (int i = 0; i < 4; ++i) {
                    const float e = __expf(fmaf(acc[mt][nt][i], INV256, -SHIFT));
                    se[mt * 2 + (i >> 1)] += e;
                    cse[nt * 2 + (i & 1)] += e;
                }
        #pragma unroll
        for (int q = 0; q < 16; ++q) {
            #pragma unroll
            for (int o = 4; o < 32; o <<= 1)
                cse[q] += __shfl_xor_sync(0xffffffffu, cse[q], o);
        }
        if (lane < 4) {          // lane == tig, g == 0
            #pragma unroll
            for (int nt = 0; nt < 8; ++nt)
                #pragma unroll
                for (int b2 = 0; b2 < 2; ++b2)
                    smc[wid][nt * 8 + lane * 2 + b2] = cse[nt * 2 + b2];
        }
    }

    #pragma unroll
    for (int s = 0; s < 4; ++s) {
        #pragma unroll
        for (int o = 1; o < 4; o <<= 1)
            se[s] += __shfl_xor_sync(0xffffffffu, se[s], o);
    }
    if (tig == 0) {
        #pragma unroll
        for (int s = 0; s < 4; ++s) se_red[wid][g][s] = se[s];
    }
    __syncthreads();

    if (tid < BM) {
        const int wm = tid >> 5;
        const int gg = (tid >> 2) & 7;
        const int ss = tid & 3;
        const int row = wm * 32 + (ss >> 1) * 16 + (ss & 1) * 8 + gg;
        g_rse[bi][it][m][row] =
            se_red[wm * 2][gg][ss] + se_red[wm * 2 + 1][gg][ss];
    } else if (m > 0) {
        const int t2 = tid - BM;             // 0..127
        const int wn = t2 >> 6, lc = t2 & 63;
        float cs = 0.f;
        #pragma unroll
        for (int wm = 0; wm < 4; ++wm) cs += smc[wm * 2 + wn][lc];
        g_cse[bi][j][m - 1][t2] = cs;
    }
}

// ---------------------------------------------------------------------------
// Kernel 4: finalize, 4 threads per row. Quad-split dot + slot sums,
// shfl merge before log, warp/block reduce, counter-elected final pass.
// ---------------------------------------------------------------------------
__global__ void __launch_bounds__(512, 2) finalize_kernel(float* __restrict__ out) {
    const int k   = blockIdx.x;
    const int b   = blockIdx.y;
    const int tid = threadIdx.x;            // 0..511
    const int r   = tid >> 2;               // row 0..127
    const int sub = tid & 3;

    __shared__ float c[DIM];
    __shared__ float ws[16];
    __shared__ int   flag;

    // batch column-sum vector: 1 component per thread, 32 half-block partials
    {
        float s = 0.f;
        #pragma unroll
        for (int p = 0; p < NTILE * 2; ++p) s += g_cpart[b][p][tid];
        c[tid] = s;
    }
    __syncthreads();

    // slot sums, split across the quad
    const int nrow = (k < 8) ? 9 : 8;
    const int ncol = (k >= 8) ? 8 : 7;
    float seT = 0.f;
    for (int d = sub; d < nrow; d += 4) seT += g_rse[b][k][d][r];
    for (int d = sub; d < ncol; d += 4) seT += g_cse[b][k][d][r];

    // partial dot over 128 components [sub*128, sub*128+128)
    const uint4* __restrict__ a4 = reinterpret_cast<const uint4*>(
        g_l8 + ((size_t)b * SEQ + (size_t)k * BM + r) * DIM) + sub * 8;
    float dot = 0.f;
    #pragma unroll
    for (int qi = 0; qi < 8; ++qi) {
        const uint4 u = __ldg(a4 + qi);
        const uint32_t w[4] = {u.x, u.y, u.z, u.w};
        #pragma unroll
        for (int wi = 0; wi < 4; ++wi) {
            const float2 f0 = fp8x2_to_f2((uint16_t)(w[wi] & 0xffffu));
            const float2 f1 = fp8x2_to_f2((uint16_t)(w[wi] >> 16));
            const float* cb = c + sub * 128 + qi * 16 + wi * 4;
            dot = fmaf(f0.x, cb[0], dot);
            dot = fmaf(f0.y, cb[1], dot);
            dot = fmaf(f1.x, cb[2], dot);
            dot = fmaf(f1.y, cb[3], dot);
        }
    }

    // merge quad before the log
    #pragma unroll
    for (int o = 1; o < 4; o <<= 1) {
        seT += __shfl_xor_sync(0xffffffffu, seT, o);
        dot += __shfl_xor_sync(0xffffffffu, dot, o);
    }
    float contrib = 0.f;
    if (sub == 0)
        contrib = (float)(SEQ - 1) * (SHIFT + logf(seT))
                - (fmaf(dot, INV256, -SHIFT));
    #pragma unroll
    for (int o = 4; o < 32; o <<= 1)
        contrib += __shfl_xor_sync(0xffffffffu, contrib, o);
    if ((tid & 31) == 0) ws[tid >> 5] = contrib;
    __syncthreads();
    if (tid < 32) {
        float v = (tid < 16) ? ws[tid] : 0.f;
        #pragma unroll
        for (int o = 8; o > 0; o >>= 1)
            v += __shfl_xor_sync(0xffffffffu, v, o);
        if (tid == 0) {
            g_partials[b * NTILE + k] = v;
            __threadfence();
            const int t = atomicAdd(&g_cnt, 1);
            flag = (t == NBLK - 1) ? 1 : 0;
        }
    }
    __syncthreads();

    if (flag && tid < 128) {
        __threadfence();
        float v = __ldcg(&g_partials[tid]);
        #pragma unroll
        for (int o = 16; o > 0; o >>= 1)
            v += __shfl_xor_sync(0xffffffffu, v, o);
        if ((tid & 31) == 0) ws[tid >> 5] = v;
        __syncwarp();
        if (tid == 0) {
            // ws[0..3] written by the 4 warps of the first 128 threads
        }
    }
    __syncthreads();
    if (flag && tid == 0) {
        const float total = ws[0] + ws[1] + ws[2] + ws[3];
        out[0] = total * (LAMBDA / ((float)BATCH * (float)SEQ * (float)SEQ));
        g_cnt = 0;                   // reset for next graph replay
    }
}

extern "C" void kernel_launch(void* const* d_in, const int* in_sizes, int n_in,
                              void* d_out, int out_size) {
    (void)in_sizes; (void)n_in; (void)out_size;
    const float* x = (const float*)d_in[0];
    float* out = (float*)d_out;

    cudaFuncSetAttribute(fused_mma_kernel,
                         cudaFuncAttributeMaxDynamicSharedMemorySize, SMEM_TOTAL);

    normalize_kernel<<<SEQ * BATCH / 8, 256>>>(x);
    colsum_kernel<<<dim3(NTILE * 2, BATCH), 128>>>();
    fused_mma_kernel<<<dim3(NJOBS, BATCH), 256, SMEM_TOTAL>>>();
    finalize_kernel<<<dim3(NTILE, BATCH), 512>>>(out);
}

// round 11
// speedup vs baseline: 12.8214x; 1.0764x over previous
#include <cuda_runtime.h>
#include <cuda_bf16.h>
#include <cuda_fp8.h>
#include <cstdint>
#include <math.h>

#define BATCH 8
#define SEQ   2048
#define DIM   512
#define BM    128
#define BN    128
#define NKP   4
#define NTILE (SEQ / BM)
#define NBLK  (BATCH * NTILE)
#define NJOBS 136

#define SCALE8     50.59644256f
#define INV256     0.00390625f
#define SHIFT      10.0f
#define LAMBDA     0.5f

#define RSTRIDE    80
#define CTILE_B    (BM * RSTRIDE)
#define SMEM_TOTAL (8 * CTILE_B)

__device__ uint8_t g_l8[BATCH * SEQ * DIM];
__device__ float g_rse[BATCH][NTILE][9][BM];
__device__ float g_cse[BATCH][NTILE][8][BM];
__device__ float g_cpart[BATCH][NTILE * 2][DIM];
__device__ float g_partials[NBLK];
__device__ int   g_cnt;

__device__ __forceinline__ uint32_t smem_u32(const void* p) {
    uint32_t a;
    asm("{ .reg .u64 t; cvta.to.shared.u64 t, %1; cvt.u32.u64 %0, t; }"
        : "=r"(a) : "l"(p));
    return a;
}
#define CP16(d, s) \
    asm volatile("cp.async.cg.shared.global [%0], [%1], 16;" :: "r"(d), "l"(s))
#define CP_COMMIT() asm volatile("cp.async.commit_group;" ::: "memory")
#define CP_WAIT(n)  asm volatile("cp.async.wait_group %0;" :: "n"(n) : "memory")

__device__ __forceinline__ void ldsm4(uint32_t* r, uint32_t addr) {
    asm volatile("ldmatrix.sync.aligned.m8n8.x4.shared.b16 {%0,%1,%2,%3}, [%4];"
                 : "=r"(r[0]), "=r"(r[1]), "=r"(r[2]), "=r"(r[3]) : "r"(addr));
}
__device__ __forceinline__ void mma16832(float* d, const uint32_t* a,
                                         uint32_t b0, uint32_t b1) {
    asm volatile(
        "mma.sync.aligned.m16n8k32.row.col.f32.e4m3.e4m3.f32 "
        "{%0,%1,%2,%3}, {%4,%5,%6,%7}, {%8,%9}, {%0,%1,%2,%3};"
        : "+f"(d[0]), "+f"(d[1]), "+f"(d[2]), "+f"(d[3])
        : "r"(a[0]), "r"(a[1]), "r"(a[2]), "r"(a[3]), "r"(b0), "r"(b1));
}
__device__ __forceinline__ float2 fp8x2_to_f2(uint16_t v) {
    const __half2_raw h = __nv_cvt_fp8x2_to_halfraw2((__nv_fp8x2_storage_t)v,
                                                     __NV_E4M3);
    return __half22float2(*reinterpret_cast<const __half2*>(&h));
}

// ---------------------------------------------------------------------------
__global__ void normalize_kernel(const float* __restrict__ x) {
    const int wid  = threadIdx.x >> 5;
    const int lane = threadIdx.x & 31;
    const int row  = blockIdx.x * 8 + wid;
    const float4* __restrict__ xr =
        reinterpret_cast<const float4*>(x + (size_t)row * DIM) + lane * 4;
    float4 v[4];
    float ss = 0.f;
    #pragma unroll
    for (int q = 0; q < 4; ++q) {
        v[q] = xr[q];
        ss = fmaf(v[q].x, v[q].x, ss);
        ss = fmaf(v[q].y, v[q].y, ss);
        ss = fmaf(v[q].z, v[q].z, ss);
        ss = fmaf(v[q].w, v[q].w, ss);
    }
    #pragma unroll
    for (int o = 16; o > 0; o >>= 1) ss += __shfl_xor_sync(0xffffffffu, ss, o);
    const float inv = SCALE8 / fmaxf(sqrtf(ss), 1e-8f);
    uint32_t w[4];
    #pragma unroll
    for (int q = 0; q < 4; ++q) {
        const __nv_fp8x2_storage_t p01 = __nv_cvt_float2_to_fp8x2(
            make_float2(v[q].x * inv, v[q].y * inv), __NV_SATFINITE, __NV_E4M3);
        const __nv_fp8x2_storage_t p23 = __nv_cvt_float2_to_fp8x2(
            make_float2(v[q].z * inv, v[q].w * inv), __NV_SATFINITE, __NV_E4M3);
        w[q] = (uint32_t)p01 | ((uint32_t)p23 << 16);
    }
    uint4 o4;
    o4.x = w[0]; o4.y = w[1]; o4.z = w[2]; o4.w = w[3];
    *reinterpret_cast<uint4*>(g_l8 + (size_t)row * DIM + lane * 16) = o4;
}

// ---------------------------------------------------------------------------
__global__ void colsum_kernel() {
    const int kh = blockIdx.x;
    const int b  = blockIdx.y;
    const int t  = threadIdx.x;
    const uint32_t* __restrict__ p = reinterpret_cast<const uint32_t*>(
        g_l8 + ((size_t)b * SEQ + (size_t)kh * 64) * DIM) + t;
    float s0 = 0.f, s1 = 0.f, s2 = 0.f, s3 = 0.f;
    #pragma unroll 8
    for (int r = 0; r < 64; ++r) {
        const uint32_t w = __ldg(p + r * (DIM / 4));
        const float2 f0 = fp8x2_to_f2((uint16_t)(w & 0xffffu));
        const float2 f1 = fp8x2_to_f2((uint16_t)(w >> 16));
        s0 += f0.x; s1 += f0.y; s2 += f1.x; s3 += f1.y;
    }
    float4 o;
    o.x = s0; o.y = s1; o.z = s2; o.w = s3;
    *reinterpret_cast<float4*>(&g_cpart[b][kh][t * 4]) = o;
}

// ---------------------------------------------------------------------------
__global__ void __launch_bounds__(256, 2) fused_mma_kernel() {
    extern __shared__ char smem[];
    const uint32_t sb  = smem_u32(smem);
    const int tid  = threadIdx.x;
    const int wid  = tid >> 5;
    const int lane = tid & 31;
    const int warp_m = wid >> 1;
    const int warp_n = wid & 1;
    const int bi = blockIdx.y;

    int it, m;
    if (blockIdx.x < 72) { it = blockIdx.x / 9; m = blockIdx.x % 9; }
    else { const int t2 = blockIdx.x - 72; it = 8 + t2 / 8; m = t2 % 8; }
    const int j = (it + m) & 15;

    const int g   = lane >> 2;
    const int tig = lane & 3;

    const uint8_t* __restrict__ base = g_l8 + (size_t)bi * SEQ * DIM;
    const uint8_t* __restrict__ Ab   = base + (size_t)(it * BM) * DIM;
    const uint8_t* __restrict__ Bb   = base + (size_t)(j * BN) * DIM;

    auto load_stage = [&](int stage, int kp) {
        const uint32_t sbase = sb + stage * 4 * CTILE_B;
        #pragma unroll
        for (int u = 0; u < 8; ++u) {
            const int p  = tid + u * 256;
            const int ch = p >> 9;
            const int rem = p & 511;
            const int r = rem >> 2, c = rem & 3;
            const uint8_t* src = (ch < 2 ? Ab : Bb)
                + (size_t)r * DIM + kp * 128 + (ch & 1) * 64 + c * 16;
            CP16(sbase + ch * CTILE_B + r * RSTRIDE + c * 16, src);
        }
        CP_COMMIT();
    };

    load_stage(0, 0);

    const int lrow = lane & 15;
    const int lsel = (lane >> 4) & 1;

    float acc[2][8][4];
    #pragma unroll
    for (int mt = 0; mt < 2; ++mt)
        #pragma unroll
        for (int nt = 0; nt < 8; ++nt)
            #pragma unroll
            for (int i = 0; i < 4; ++i) acc[mt][nt][i] = 0.f;

    for (int kp = 0; kp < NKP; ++kp) {
        if (kp + 1 < NKP) {
            load_stage((kp + 1) & 1, kp + 1);
            CP_WAIT(1);
        } else {
            CP_WAIT(0);
        }
        __syncthreads();

        #pragma unroll
        for (int cc = 0; cc < 2; ++cc) {
            const uint32_t abase = sb + ((kp & 1) * 4 + cc) * CTILE_B;
            const uint32_t bbase = sb + ((kp & 1) * 4 + 2 + cc) * CTILE_B;
            #pragma unroll
            for (int ks = 0; ks < 2; ++ks) {
                uint32_t af[2][4];
                #pragma unroll
                for (int mt = 0; mt < 2; ++mt)
                    ldsm4(af[mt], abase
                          + (warp_m * 32 + mt * 16 + lrow) * RSTRIDE
                          + ks * 32 + lsel * 16);
                uint32_t bx[4][4];
                #pragma unroll
                for (int q = 0; q < 4; ++q)
                    ldsm4(bx[q], bbase
                          + (warp_n * 64 + q * 16 + lrow) * RSTRIDE
                          + ks * 32 + lsel * 16);
                #pragma unroll
                for (int mt = 0; mt < 2; ++mt)
                    #pragma unroll
                    for (int nt = 0; nt < 8; ++nt) {
                        const int q = nt >> 1, e = nt & 1;
                        mma16832(acc[mt][nt], af[mt], bx[q][e], bx[q][e + 2]);
                    }
            }
        }
        __syncthreads();
    }

    __shared__ float smc[8][64];
    __shared__ float se_red[8][8][4];

    float se[4];
    #pragma unroll
    for (int s = 0; s < 4; ++s) se[s] = 0.f;

    if (m == 0) {
        #pragma unroll
        for (int mt = 0; mt < 2; ++mt)
            #pragma unroll
            for (int nt = 0; nt < 8; ++nt)
                #pragma unroll
                for (int i = 0; i < 4; ++i) {
                    const int lr = warp_m * 32 + mt * 16 + (i >> 1) * 8 + g;
                    const int lc = warp_n * 64 + nt * 8 + tig * 2 + (i & 1);
                    if (lr != lc)
                        se[mt * 2 + (i >> 1)] +=
                            __expf(fmaf(acc[mt][nt][i], INV256, -SHIFT));
                }
    } else {
        float cse[16];
        #pragma unroll
        for (int q = 0; q < 16; ++q) cse[q] = 0.f;
        #pragma unroll
        for (int mt = 0; mt < 2; ++mt)
            #pragma unroll
            for (int nt = 0; nt < 8; ++nt)
                #pragma unroll
                for (int i = 0; i < 4; ++i) {
                    const float e = __expf(fmaf(acc[mt][nt][i], INV256, -SHIFT));
                    se[mt * 2 + (i >> 1)] += e;
                    cse[nt * 2 + (i & 1)] += e;
                }
        #pragma unroll
        for (int q = 0; q < 16; ++q) {
            #pragma unroll
            for (int o = 4; o < 32; o <<= 1)
                cse[q] += __shfl_xor_sync(0xffffffffu, cse[q], o);
        }
        if (lane < 4) {
            #pragma unroll
            for (int nt = 0; nt < 8; ++nt)
                #pragma unroll
                for (int b2 = 0; b2 < 2; ++b2)
                    smc[wid][nt * 8 + lane * 2 + b2] = cse[nt * 2 + b2];
        }
    }

    #pragma unroll
    for (int s = 0; s < 4; ++s) {
        #pragma unroll
        for (int o = 1; o < 4; o <<= 1)
            se[s] += __shfl_xor_sync(0xffffffffu, se[s], o);
    }
    if (tig == 0) {
        #pragma unroll
        for (int s = 0; s < 4; ++s) se_red[wid][g][s] = se[s];
    }
    __syncthreads();

    if (tid < BM) {
        const int wm = tid >> 5;
        const int gg = (tid >> 2) & 7;
        const int ss = tid & 3;
        const int row = wm * 32 + (ss >> 1) * 16 + (ss & 1) * 8 + gg;
        g_rse[bi][it][m][row] =
            se_red[wm * 2][gg][ss] + se_red[wm * 2 + 1][gg][ss];
    } else if (m > 0) {
        const int t2 = tid - BM;
        const int wn = t2 >> 6, lc = t2 & 63;
        float cs = 0.f;
        #pragma unroll
        for (int wm = 0; wm < 4; ++wm) cs += smc[wm * 2 + wn][lc];
        g_cse[bi][j][m - 1][t2] = cs;
    }
}

// ---------------------------------------------------------------------------
// Kernel 4: finalize. Per (b,k): 17 slot loads per row, log, reduce.
// Block k==0 adds the batch term SHIFT*SEQ - |c_b|^2/256 (analytic rowsum).
// ---------------------------------------------------------------------------
__global__ void __launch_bounds__(512, 2) finalize_kernel(float* __restrict__ out) {
    const int k   = blockIdx.x;
    const int b   = blockIdx.y;
    const int tid = threadIdx.x;
    const int r   = tid >> 2;
    const int sub = tid & 3;

    __shared__ float ws[16];
    __shared__ int   flag;

    const int nrow = (k < 8) ? 9 : 8;
    const int ncol = (k >= 8) ? 8 : 7;
    float seT = 0.f;
    for (int d = sub; d < nrow; d += 4) seT += g_rse[b][k][d][r];
    for (int d = sub; d < ncol; d += 4) seT += g_cse[b][k][d][r];
    #pragma unroll
    for (int o = 1; o < 4; o <<= 1)
        seT += __shfl_xor_sync(0xffffffffu, seT, o);

    float contrib = 0.f;
    if (sub == 0)
        contrib = (float)(SEQ - 1) * (SHIFT + logf(seT));

    if (k == 0) {
        // batch analytic-rowsum term: each thread owns component `tid` of c_b
        float c = 0.f;
        #pragma unroll
        for (int p = 0; p < NTILE * 2; ++p) c += g_cpart[b][p][tid];
        float sqs = c * c;
        #pragma unroll
        for (int o = 1; o < 4; o <<= 1)
            sqs += __shfl_xor_sync(0xffffffffu, sqs, o);
        if (sub == 0)
            contrib += (SHIFT * (float)SEQ) * (1.0f / 128.0f) - sqs * INV256;
    }

    #pragma unroll
    for (int o = 4; o < 32; o <<= 1)
        contrib += __shfl_xor_sync(0xffffffffu, contrib, o);
    if ((tid & 31) == 0) ws[tid >> 5] = contrib;
    __syncthreads();
    if (tid < 32) {
        float v = (tid < 16) ? ws[tid] : 0.f;
        #pragma unroll
        for (int o = 8; o > 0; o >>= 1)
            v += __shfl_xor_sync(0xffffffffu, v, o);
        if (tid == 0) {
            g_partials[b * NTILE + k] = v;
            __threadfence();
            const int t = atomicAdd(&g_cnt, 1);
            flag = (t == NBLK - 1) ? 1 : 0;
        }
    }
    __syncthreads();

    if (flag) {
        if (tid < 128) {
            __threadfence();
            float v = __ldcg(&g_partials[tid]);
            #pragma unroll
            for (int o = 16; o > 0; o >>= 1)
                v += __shfl_xor_sync(0xffffffffu, v, o);
            if ((tid & 31) == 0) ws[tid >> 5] = v;
        }
        __syncthreads();
        if (tid == 0) {
            const float total = ws[0] + ws[1] + ws[2] + ws[3];
            out[0] = total * (LAMBDA / ((float)BATCH * (float)SEQ * (float)SEQ));
            g_cnt = 0;
        }
    }
}

extern "C" void kernel_launch(void* const* d_in, const int* in_sizes, int n_in,
                              void* d_out, int out_size) {
    (void)in_sizes; (void)n_in; (void)out_size;
    const float* x = (const float*)d_in[0];
    float* out = (float*)d_out;

    cudaFuncSetAttribute(fused_mma_kernel,
                         cudaFuncAttributeMaxDynamicSharedMemorySize, SMEM_TOTAL);

    normalize_kernel<<<SEQ * BATCH / 8, 256>>>(x);
    colsum_kernel<<<dim3(NTILE * 2, BATCH), 128>>>();
    fused_mma_kernel<<<dim3(NJOBS, BATCH), 256, SMEM_TOTAL>>>();
    finalize_kernel<<<dim3(NTILE, BATCH), 512>>>(out);
}

// round 12
// speedup vs baseline: 12.8447x; 1.0018x over previous
#include <cuda_runtime.h>
#include <cuda_bf16.h>
#include <cuda_fp8.h>
#include <cstdint>
#include <math.h>

#define BATCH 8
#define SEQ   2048
#define DIM   512
#define BM    128
#define BN    128
#define NKP   4
#define NTILE (SEQ / BM)
#define NBLK  (BATCH * NTILE)
#define NJOBS 136                    // per batch
#define TOTJOBS (NJOBS * BATCH)      // 1088
#define NPERS 296                    // persistent CTAs (2 per SM)

#define SCALE8     50.59644256f
#define INV256     0.00390625f
#define SHIFT      10.0f
#define LAMBDA     0.5f

#define RSTRIDE    80
#define CTILE_B    (BM * RSTRIDE)
#define SMEM_TOTAL (8 * CTILE_B)

__device__ uint8_t g_l8[BATCH * SEQ * DIM];
__device__ float g_rse[BATCH][NTILE][9][BM];
__device__ float g_cse[BATCH][NTILE][8][BM];
__device__ float g_cpart[BATCH][NTILE * 2][DIM];
__device__ float g_partials[NBLK];
__device__ int   g_cnt;
__device__ int   g_ticket;

__device__ __forceinline__ uint32_t smem_u32(const void* p) {
    uint32_t a;
    asm("{ .reg .u64 t; cvta.to.shared.u64 t, %1; cvt.u32.u64 %0, t; }"
        : "=r"(a) : "l"(p));
    return a;
}
#define CP16(d, s) \
    asm volatile("cp.async.cg.shared.global [%0], [%1], 16;" :: "r"(d), "l"(s))
#define CP_COMMIT() asm volatile("cp.async.commit_group;" ::: "memory")
#define CP_WAIT(n)  asm volatile("cp.async.wait_group %0;" :: "n"(n) : "memory")

__device__ __forceinline__ void ldsm4(uint32_t* r, uint32_t addr) {
    asm volatile("ldmatrix.sync.aligned.m8n8.x4.shared.b16 {%0,%1,%2,%3}, [%4];"
                 : "=r"(r[0]), "=r"(r[1]), "=r"(r[2]), "=r"(r[3]) : "r"(addr));
}
__device__ __forceinline__ void mma16832(float* d, const uint32_t* a,
                                         uint32_t b0, uint32_t b1) {
    asm volatile(
        "mma.sync.aligned.m16n8k32.row.col.f32.e4m3.e4m3.f32 "
        "{%0,%1,%2,%3}, {%4,%5,%6,%7}, {%8,%9}, {%0,%1,%2,%3};"
        : "+f"(d[0]), "+f"(d[1]), "+f"(d[2]), "+f"(d[3])
        : "r"(a[0]), "r"(a[1]), "r"(a[2]), "r"(a[3]), "r"(b0), "r"(b1));
}
__device__ __forceinline__ float2 fp8x2_to_f2(uint16_t v) {
    const __half2_raw h = __nv_cvt_fp8x2_to_halfraw2((__nv_fp8x2_storage_t)v,
                                                     __NV_E4M3);
    return __half22float2(*reinterpret_cast<const __half2*>(&h));
}

// ---------------------------------------------------------------------------
// Kernel 1: warp-per-row L2-normalize, fold 16*sqrt(1/T), emit e4m3.
// ---------------------------------------------------------------------------
__global__ void normalize_kernel(const float* __restrict__ x) {
    const int wid  = threadIdx.x >> 5;
    const int lane = threadIdx.x & 31;
    const int row  = blockIdx.x * 8 + wid;
    const float4* __restrict__ xr =
        reinterpret_cast<const float4*>(x + (size_t)row * DIM) + lane * 4;
    float4 v[4];
    float ss = 0.f;
    #pragma unroll
    for (int q = 0; q < 4; ++q) {
        v[q] = xr[q];
        ss = fmaf(v[q].x, v[q].x, ss);
        ss = fmaf(v[q].y, v[q].y, ss);
        ss = fmaf(v[q].z, v[q].z, ss);
        ss = fmaf(v[q].w, v[q].w, ss);
    }
    #pragma unroll
    for (int o = 16; o > 0; o >>= 1) ss += __shfl_xor_sync(0xffffffffu, ss, o);
    const float inv = SCALE8 / fmaxf(sqrtf(ss), 1e-8f);
    uint32_t w[4];
    #pragma unroll
    for (int q = 0; q < 4; ++q) {
        const __nv_fp8x2_storage_t p01 = __nv_cvt_float2_to_fp8x2(
            make_float2(v[q].x * inv, v[q].y * inv), __NV_SATFINITE, __NV_E4M3);
        const __nv_fp8x2_storage_t p23 = __nv_cvt_float2_to_fp8x2(
            make_float2(v[q].z * inv, v[q].w * inv), __NV_SATFINITE, __NV_E4M3);
        w[q] = (uint32_t)p01 | ((uint32_t)p23 << 16);
    }
    uint4 o4;
    o4.x = w[0]; o4.y = w[1]; o4.z = w[2]; o4.w = w[3];
    *reinterpret_cast<uint4*>(g_l8 + (size_t)row * DIM + lane * 16) = o4;
}

// ---------------------------------------------------------------------------
// Kernel 2: half-block (64-row) column sums (feeds |c_b|^2).
// ---------------------------------------------------------------------------
__global__ void colsum_kernel() {
    const int kh = blockIdx.x;
    const int b  = blockIdx.y;
    const int t  = threadIdx.x;
    const uint32_t* __restrict__ p = reinterpret_cast<const uint32_t*>(
        g_l8 + ((size_t)b * SEQ + (size_t)kh * 64) * DIM) + t;
    float s0 = 0.f, s1 = 0.f, s2 = 0.f, s3 = 0.f;
    #pragma unroll 8
    for (int r = 0; r < 64; ++r) {
        const uint32_t w = __ldg(p + r * (DIM / 4));
        const float2 f0 = fp8x2_to_f2((uint16_t)(w & 0xffffu));
        const float2 f1 = fp8x2_to_f2((uint16_t)(w >> 16));
        s0 += f0.x; s1 += f0.y; s2 += f1.x; s3 += f1.y;
    }
    float4 o;
    o.x = s0; o.y = s1; o.z = s2; o.w = s3;
    *reinterpret_cast<float4*>(&g_cpart[b][kh][t * 4]) = o;
}

// ---------------------------------------------------------------------------
// Kernel 3: PERSISTENT tile GEMM. 296 CTAs pull 1088 jobs via ticket.
// Result slots are keyed by job id -> deterministic regardless of scheduling.
// ---------------------------------------------------------------------------
__global__ void __launch_bounds__(256, 2) fused_mma_kernel() {
    extern __shared__ char smem[];
    const uint32_t sb  = smem_u32(smem);
    const int tid  = threadIdx.x;
    const int wid  = tid >> 5;
    const int lane = tid & 31;
    const int warp_m = wid >> 1;
    const int warp_n = wid & 1;

    const int g   = lane >> 2;
    const int tig = lane & 3;
    const int lrow = lane & 15;
    const int lsel = (lane >> 4) & 1;

    __shared__ int   job_s;
    __shared__ float smc[8][64];
    __shared__ float se_red[8][8][4];

    for (;;) {
        if (tid == 0) job_s = atomicAdd(&g_ticket, 1);
        __syncthreads();
        const int job = job_s;
        if (job >= TOTJOBS) break;

        const int bi = job / NJOBS;
        const int jx = job - bi * NJOBS;
        int it, m;
        if (jx < 72) { it = jx / 9; m = jx % 9; }
        else { const int t2 = jx - 72; it = 8 + t2 / 8; m = t2 % 8; }
        const int j = (it + m) & 15;

        const uint8_t* __restrict__ base = g_l8 + (size_t)bi * SEQ * DIM;
        const uint8_t* __restrict__ Ab   = base + (size_t)(it * BM) * DIM;
        const uint8_t* __restrict__ Bb   = base + (size_t)(j * BN) * DIM;

        auto load_stage = [&](int stage, int kp) {
            const uint32_t sbase = sb + stage * 4 * CTILE_B;
            #pragma unroll
            for (int u = 0; u < 8; ++u) {
                const int p  = tid + u * 256;
                const int ch = p >> 9;
                const int rem = p & 511;
                const int r = rem >> 2, c = rem & 3;
                const uint8_t* src = (ch < 2 ? Ab : Bb)
                    + (size_t)r * DIM + kp * 128 + (ch & 1) * 64 + c * 16;
                CP16(sbase + ch * CTILE_B + r * RSTRIDE + c * 16, src);
            }
            CP_COMMIT();
        };

        load_stage(0, 0);

        float acc[2][8][4];
        #pragma unroll
        for (int mt = 0; mt < 2; ++mt)
            #pragma unroll
            for (int nt = 0; nt < 8; ++nt)
                #pragma unroll
                for (int i = 0; i < 4; ++i) acc[mt][nt][i] = 0.f;

        for (int kp = 0; kp < NKP; ++kp) {
            if (kp + 1 < NKP) {
                load_stage((kp + 1) & 1, kp + 1);
                CP_WAIT(1);
            } else {
                CP_WAIT(0);
            }
            __syncthreads();

            #pragma unroll
            for (int cc = 0; cc < 2; ++cc) {
                const uint32_t abase = sb + ((kp & 1) * 4 + cc) * CTILE_B;
                const uint32_t bbase = sb + ((kp & 1) * 4 + 2 + cc) * CTILE_B;
                #pragma unroll
                for (int ks = 0; ks < 2; ++ks) {
                    uint32_t af[2][4];
                    #pragma unroll
                    for (int mt = 0; mt < 2; ++mt)
                        ldsm4(af[mt], abase
                              + (warp_m * 32 + mt * 16 + lrow) * RSTRIDE
                              + ks * 32 + lsel * 16);
                    uint32_t bx[4][4];
                    #pragma unroll
                    for (int q = 0; q < 4; ++q)
                        ldsm4(bx[q], bbase
                              + (warp_n * 64 + q * 16 + lrow) * RSTRIDE
                              + ks * 32 + lsel * 16);
                    #pragma unroll
                    for (int mt = 0; mt < 2; ++mt)
                        #pragma unroll
                        for (int nt = 0; nt < 8; ++nt) {
                            const int q = nt >> 1, e = nt & 1;
                            mma16832(acc[mt][nt], af[mt], bx[q][e], bx[q][e + 2]);
                        }
                }
            }
            __syncthreads();
        }

        // ---- fused two-sided epilogue (sumexp only; v = acc/256) ----
        float se[4];
        #pragma unroll
        for (int s = 0; s < 4; ++s) se[s] = 0.f;

        if (m == 0) {
            #pragma unroll
            for (int mt = 0; mt < 2; ++mt)
                #pragma unroll
                for (int nt = 0; nt < 8; ++nt)
                    #pragma unroll
                    for (int i = 0; i < 4; ++i) {
                        const int lr = warp_m * 32 + mt * 16 + (i >> 1) * 8 + g;
                        const int lc = warp_n * 64 + nt * 8 + tig * 2 + (i & 1);
                        if (lr != lc)
                            se[mt * 2 + (i >> 1)] +=
                                __expf(fmaf(acc[mt][nt][i], INV256, -SHIFT));
                    }
        } else {
            float cse[16];
            #pragma unroll
            for (int q = 0; q < 16; ++q) cse[q] = 0.f;
            #pragma unroll
            for (int mt = 0; mt < 2; ++mt)
                #pragma unroll
                for (int nt = 0; nt < 8; ++nt)
                    #pragma unroll
                    for (int i = 0; i < 4; ++i) {
                        const float e =
                            __expf(fmaf(acc[mt][nt][i], INV256, -SHIFT));
                        se[mt * 2 + (i >> 1)] += e;
                        cse[nt * 2 + (i & 1)] += e;
                    }
            #pragma unroll
            for (int q = 0; q < 16; ++q) {
                #pragma unroll
                for (int o = 4; o < 32; o <<= 1)
                    cse[q] += __shfl_xor_sync(0xffffffffu, cse[q], o);
            }
            if (lane < 4) {
                #pragma unroll
                for (int nt = 0; nt < 8; ++nt)
                    #pragma unroll
                    for (int b2 = 0; b2 < 2; ++b2)
                        smc[wid][nt * 8 + lane * 2 + b2] = cse[nt * 2 + b2];
            }
        }

        #pragma unroll
        for (int s = 0; s < 4; ++s) {
            #pragma unroll
            for (int o = 1; o < 4; o <<= 1)
                se[s] += __shfl_xor_sync(0xffffffffu, se[s], o);
        }
        if (tig == 0) {
            #pragma unroll
            for (int s = 0; s < 4; ++s) se_red[wid][g][s] = se[s];
        }
        __syncthreads();

        if (tid < BM) {
            const int wm = tid >> 5;
            const int gg = (tid >> 2) & 7;
            const int ss = tid & 3;
            const int row = wm * 32 + (ss >> 1) * 16 + (ss & 1) * 8 + gg;
            g_rse[bi][it][m][row] =
                se_red[wm * 2][gg][ss] + se_red[wm * 2 + 1][gg][ss];
        } else if (m > 0) {
            const int t2 = tid - BM;
            const int wn = t2 >> 6, lc = t2 & 63;
            float cs = 0.f;
            #pragma unroll
            for (int wm = 0; wm < 4; ++wm) cs += smc[wm * 2 + wn][lc];
            g_cse[bi][j][m - 1][t2] = cs;
        }
        __syncthreads();        // protect smc/se_red/job_s before next job
    }
}

// ---------------------------------------------------------------------------
// Kernel 4: finalize. 16 slots per row (nrow+ncol==16 always), 4 per quad-sub,
// fully unrolled. Block k==0 adds SHIFT*SEQ - |c_b|^2/256. Elected tail does
// the deterministic final sum and resets both counters.
// ---------------------------------------------------------------------------
__global__ void __launch_bounds__(512, 2) finalize_kernel(float* __restrict__ out) {
    const int k   = blockIdx.x;
    const int b   = blockIdx.y;
    const int tid = threadIdx.x;
    const int r   = tid >> 2;
    const int sub = tid & 3;

    __shared__ float ws[16];
    __shared__ int   flag;

    const int nrow = (k < 8) ? 9 : 8;
    float seT = 0.f;
    #pragma unroll
    for (int u = 0; u < 4; ++u) {
        const int s = sub * 4 + u;          // 0..15
        const float v = (s < nrow) ? g_rse[b][k][s][r]
                                   : g_cse[b][k][s - nrow][r];
        seT += v;
    }
    #pragma unroll
    for (int o = 1; o < 4; o <<= 1)
        seT += __shfl_xor_sync(0xffffffffu, seT, o);

    float contrib = 0.f;
    if (sub == 0)
        contrib = (float)(SEQ - 1) * (SHIFT + logf(seT));

    if (k == 0) {
        float c = 0.f;
        #pragma unroll
        for (int p = 0; p < NTILE * 2; ++p) c += g_cpart[b][p][tid];
        float sqs = c * c;
        #pragma unroll
        for (int o = 1; o < 4; o <<= 1)
            sqs += __shfl_xor_sync(0xffffffffu, sqs, o);
        if (sub == 0)
            contrib += (SHIFT * (float)SEQ) * (1.0f / 128.0f) - sqs * INV256;
    }

    #pragma unroll
    for (int o = 4; o < 32; o <<= 1)
        contrib += __shfl_xor_sync(0xffffffffu, contrib, o);
    if ((tid & 31) == 0) ws[tid >> 5] = contrib;
    __syncthreads();
    if (tid < 32) {
        float v = (tid < 16) ? ws[tid] : 0.f;
        #pragma unroll
        for (int o = 8; o > 0; o >>= 1)
            v += __shfl_xor_sync(0xffffffffu, v, o);
        if (tid == 0) {
            g_partials[b * NTILE + k] = v;
            __threadfence();
            const int t = atomicAdd(&g_cnt, 1);
            flag = (t == NBLK - 1) ? 1 : 0;
        }
    }
    __syncthreads();

    if (flag) {
        if (tid < 128) {
            __threadfence();
            float v = __ldcg(&g_partials[tid]);
            #pragma unroll
            for (int o = 16; o > 0; o >>= 1)
                v += __shfl_xor_sync(0xffffffffu, v, o);
            if ((tid & 31) == 0) ws[tid >> 5] = v;
        }
        __syncthreads();
        if (tid == 0) {
            const float total = ws[0] + ws[1] + ws[2] + ws[3];
            out[0] = total * (LAMBDA / ((float)BATCH * (float)SEQ * (float)SEQ));
            g_cnt = 0;
            g_ticket = 0;            // reset persistent-GEMM ticket for replay
        }
    }
}

extern "C" void kernel_launch(void* const* d_in, const int* in_sizes, int n_in,
                              void* d_out, int out_size) {
    (void)in_sizes; (void)n_in; (void)out_size;
    const float* x = (const float*)d_in[0];
    float* out = (float*)d_out;

    cudaFuncSetAttribute(fused_mma_kernel,
                         cudaFuncAttributeMaxDynamicSharedMemorySize, SMEM_TOTAL);

    normalize_kernel<<<SEQ * BATCH / 8, 256>>>(x);
    colsum_kernel<<<dim3(NTILE * 2, BATCH), 128>>>();
    fused_mma_kernel<<<NPERS, 256, SMEM_TOTAL>>>();
    finalize_kernel<<<dim3(NTILE, BATCH), 512>>>(out);
}

// round 13
// speedup vs baseline: 13.0869x; 1.0189x over previous
#include <cuda_runtime.h>
#include <cuda_bf16.h>
#include <cuda_fp8.h>
#include <cstdint>
#include <math.h>

#define BATCH 8
#define SEQ   2048
#define DIM   512
#define BM    128
#define BN    128
#define NKP   4
#define NTILE (SEQ / BM)
#define NBLK  (BATCH * NTILE)
#define NJOBS 136                    // per batch
#define TOTJOBS (NJOBS * BATCH)      // 1088
#define NPERS 296                    // persistent CTAs (2 per SM)

#define SCALE8     50.59644256f
#define INV256     0.00390625f
#define SHIFT      10.0f
#define LAMBDA     0.5f

#define RSTRIDE    80
#define CTILE_B    (BM * RSTRIDE)
#define SMEM_TOTAL (8 * CTILE_B)

__device__ uint8_t g_l8[BATCH * SEQ * DIM];
__device__ float g_rse[BATCH][NTILE][9][BM];
__device__ float g_cse[BATCH][NTILE][8][BM];
__device__ float g_cpart[BATCH][NTILE * 2][DIM];
__device__ float g_partials[NBLK];
__device__ int   g_cnt;
__device__ int   g_ticket;

__device__ __forceinline__ uint32_t smem_u32(const void* p) {
    uint32_t a;
    asm("{ .reg .u64 t; cvta.to.shared.u64 t, %1; cvt.u32.u64 %0, t; }"
        : "=r"(a) : "l"(p));
    return a;
}
#define CP16(d, s) \
    asm volatile("cp.async.cg.shared.global [%0], [%1], 16;" :: "r"(d), "l"(s))
#define CP_COMMIT() asm volatile("cp.async.commit_group;" ::: "memory")
#define CP_WAIT(n)  asm volatile("cp.async.wait_group %0;" :: "n"(n) : "memory")

__device__ __forceinline__ void ldsm4(uint32_t* r, uint32_t addr) {
    asm volatile("ldmatrix.sync.aligned.m8n8.x4.shared.b16 {%0,%1,%2,%3}, [%4];"
                 : "=r"(r[0]), "=r"(r[1]), "=r"(r[2]), "=r"(r[3]) : "r"(addr));
}
__device__ __forceinline__ void mma16832(float* d, const uint32_t* a,
                                         uint32_t b0, uint32_t b1) {
    asm volatile(
        "mma.sync.aligned.m16n8k32.row.col.f32.e4m3.e4m3.f32 "
        "{%0,%1,%2,%3}, {%4,%5,%6,%7}, {%8,%9}, {%0,%1,%2,%3};"
        : "+f"(d[0]), "+f"(d[1]), "+f"(d[2]), "+f"(d[3])
        : "r"(a[0]), "r"(a[1]), "r"(a[2]), "r"(a[3]), "r"(b0), "r"(b1));
}
__device__ __forceinline__ float2 fp8x2_to_f2(uint16_t v) {
    const __half2_raw h = __nv_cvt_fp8x2_to_halfraw2((__nv_fp8x2_storage_t)v,
                                                     __NV_E4M3);
    return __half22float2(*reinterpret_cast<const __half2*>(&h));
}
__device__ __forceinline__ float fp8_to_f32(uint8_t b) {
    __half_raw h = __nv_cvt_fp8_to_halfraw((__nv_fp8_storage_t)b, __NV_E4M3);
    return __half2float(*reinterpret_cast<__half*>(&h));
}

// ---------------------------------------------------------------------------
// Kernel 1: warp-per-row L2-normalize, fold 16*sqrt(1/T), emit e4m3.
// ---------------------------------------------------------------------------
__global__ void normalize_kernel(const float* __restrict__ x) {
    const int wid  = threadIdx.x >> 5;
    const int lane = threadIdx.x & 31;
    const int row  = blockIdx.x * 8 + wid;
    const float4* __restrict__ xr =
        reinterpret_cast<const float4*>(x + (size_t)row * DIM) + lane * 4;
    float4 v[4];
    float ss = 0.f;
    #pragma unroll
    for (int q = 0; q < 4; ++q) {
        v[q] = xr[q];
        ss = fmaf(v[q].x, v[q].x, ss);
        ss = fmaf(v[q].y, v[q].y, ss);
        ss = fmaf(v[q].z, v[q].z, ss);
        ss = fmaf(v[q].w, v[q].w, ss);
    }
    #pragma unroll
    for (int o = 16; o > 0; o >>= 1) ss += __shfl_xor_sync(0xffffffffu, ss, o);
    const float inv = SCALE8 / fmaxf(sqrtf(ss), 1e-8f);
    uint32_t w[4];
    #pragma unroll
    for (int q = 0; q < 4; ++q) {
        const __nv_fp8x2_storage_t p01 = __nv_cvt_float2_to_fp8x2(
            make_float2(v[q].x * inv, v[q].y * inv), __NV_SATFINITE, __NV_E4M3);
        const __nv_fp8x2_storage_t p23 = __nv_cvt_float2_to_fp8x2(
            make_float2(v[q].z * inv, v[q].w * inv), __NV_SATFINITE, __NV_E4M3);
        w[q] = (uint32_t)p01 | ((uint32_t)p23 << 16);
    }
    uint4 o4;
    o4.x = w[0]; o4.y = w[1]; o4.z = w[2]; o4.w = w[3];
    *reinterpret_cast<uint4*>(g_l8 + (size_t)row * DIM + lane * 16) = o4;
}

// ---------------------------------------------------------------------------
// Kernel 2: PERSISTENT tile GEMM. 296 CTAs pull 1088 jobs via ticket.
// Diagonal jobs (m==0) also emit the half-block column sums from the
// staged A chunks (same bytes, same per-column row order as the old
// colsum kernel -> bit-identical g_cpart).
// ---------------------------------------------------------------------------
__global__ void __launch_bounds__(256, 2) fused_mma_kernel() {
    extern __shared__ char smem[];
    const uint32_t sb  = smem_u32(smem);
    const int tid  = threadIdx.x;
    const int wid  = tid >> 5;
    const int lane = tid & 31;
    const int warp_m = wid >> 1;
    const int warp_n = wid & 1;

    const int g   = lane >> 2;
    const int tig = lane & 3;
    const int lrow = lane & 15;
    const int lsel = (lane >> 4) & 1;

    __shared__ int   job_s;
    __shared__ float smc[8][64];
    __shared__ float se_red[8][8][4];

    for (;;) {
        if (tid == 0) job_s = atomicAdd(&g_ticket, 1);
        __syncthreads();
        const int job = job_s;
        if (job >= TOTJOBS) break;

        const int bi = job / NJOBS;
        const int jx = job - bi * NJOBS;
        int it, m;
        if (jx < 72) { it = jx / 9; m = jx % 9; }
        else { const int t2 = jx - 72; it = 8 + t2 / 8; m = t2 % 8; }
        const int j = (it + m) & 15;

        const uint8_t* __restrict__ base = g_l8 + (size_t)bi * SEQ * DIM;
        const uint8_t* __restrict__ Ab   = base + (size_t)(it * BM) * DIM;
        const uint8_t* __restrict__ Bb   = base + (size_t)(j * BN) * DIM;

        auto load_stage = [&](int stage, int kp) {
            const uint32_t sbase = sb + stage * 4 * CTILE_B;
            #pragma unroll
            for (int u = 0; u < 8; ++u) {
                const int p  = tid + u * 256;
                const int ch = p >> 9;
                const int rem = p & 511;
                const int r = rem >> 2, c = rem & 3;
                const uint8_t* src = (ch < 2 ? Ab : Bb)
                    + (size_t)r * DIM + kp * 128 + (ch & 1) * 64 + c * 16;
                CP16(sbase + ch * CTILE_B + r * RSTRIDE + c * 16, src);
            }
            CP_COMMIT();
        };

        load_stage(0, 0);

        float acc[2][8][4];
        #pragma unroll
        for (int mt = 0; mt < 2; ++mt)
            #pragma unroll
            for (int nt = 0; nt < 8; ++nt)
                #pragma unroll
                for (int i = 0; i < 4; ++i) acc[mt][nt][i] = 0.f;

        for (int kp = 0; kp < NKP; ++kp) {
            if (kp + 1 < NKP) {
                load_stage((kp + 1) & 1, kp + 1);
                CP_WAIT(1);
            } else {
                CP_WAIT(0);
            }
            __syncthreads();

            #pragma unroll
            for (int cc = 0; cc < 2; ++cc) {
                const uint32_t abase = sb + ((kp & 1) * 4 + cc) * CTILE_B;
                const uint32_t bbase = sb + ((kp & 1) * 4 + 2 + cc) * CTILE_B;
                #pragma unroll
                for (int ks = 0; ks < 2; ++ks) {
                    uint32_t af[2][4];
                    #pragma unroll
                    for (int mt = 0; mt < 2; ++mt)
                        ldsm4(af[mt], abase
                              + (warp_m * 32 + mt * 16 + lrow) * RSTRIDE
                              + ks * 32 + lsel * 16);
                    uint32_t bx[4][4];
                    #pragma unroll
                    for (int q = 0; q < 4; ++q)
                        ldsm4(bx[q], bbase
                              + (warp_n * 64 + q * 16 + lrow) * RSTRIDE
                              + ks * 32 + lsel * 16);
                    #pragma unroll
                    for (int mt = 0; mt < 2; ++mt)
                        #pragma unroll
                        for (int nt = 0; nt < 8; ++nt) {
                            const int q = nt >> 1, e = nt & 1;
                            mma16832(acc[mt][nt], af[mt], bx[q][e], bx[q][e + 2]);
                        }
                }
            }

            // ---- fused column-sum partials (diagonal jobs only) ----
            // Buffer (kp&1) is safe to read until the trailing barrier:
            // the overwriting load (for kp+2) is issued only after it.
            if (m == 0) {
                const int half = tid >> 7;          // 0: rows 0..63, 1: 64..127
                const int col  = tid & 127;         // column within this kp
                const size_t off = (size_t)((kp & 1) * 4 + (col >> 6)) * CTILE_B
                                 + (size_t)(half * 64) * RSTRIDE + (col & 63);
                float s = 0.f;
                #pragma unroll 8
                for (int r2 = 0; r2 < 64; ++r2)
                    s += fp8_to_f32((uint8_t)smem[off + (size_t)r2 * RSTRIDE]);
                g_cpart[bi][it * 2 + half][kp * 128 + col] = s;
            }
            __syncthreads();
        }

        // ---- fused two-sided epilogue (sumexp only; v = acc/256) ----
        float se[4];
        #pragma unroll
        for (int s = 0; s < 4; ++s) se[s] = 0.f;

        if (m == 0) {
            #pragma unroll
            for (int mt = 0; mt < 2; ++mt)
                #pragma unroll
                for (int nt = 0; nt < 8; ++nt)
                    #pragma unroll
                    for (int i = 0; i < 4; ++i) {
                        const int lr = warp_m * 32 + mt * 16 + (i >> 1) * 8 + g;
                        const int lc = warp_n * 64 + nt * 8 + tig * 2 + (i & 1);
                        if (lr != lc)
                            se[mt * 2 + (i >> 1)] +=
                                __expf(fmaf(acc[mt][nt][i], INV256, -SHIFT));
                    }
        } else {
            float cse[16];
            #pragma unroll
            for (int q = 0; q < 16; ++q) cse[q] = 0.f;
            #pragma unroll
            for (int mt = 0; mt < 2; ++mt)
                #pragma unroll
                for (int nt = 0; nt < 8; ++nt)
                    #pragma unroll
                    for (int i = 0; i < 4; ++i) {
                        const float e =
                            __expf(fmaf(acc[mt][nt][i], INV256, -SHIFT));
                        se[mt * 2 + (i >> 1)] += e;
                        cse[nt * 2 + (i & 1)] += e;
                    }
            #pragma unroll
            for (int q = 0; q < 16; ++q) {
                #pragma unroll
                for (int o = 4; o < 32; o <<= 1)
                    cse[q] += __shfl_xor_sync(0xffffffffu, cse[q], o);
            }
            if (lane < 4) {
                #pragma unroll
                for (int nt = 0; nt < 8; ++nt)
                    #pragma unroll
                    for (int b2 = 0; b2 < 2; ++b2)
                        smc[wid][nt * 8 + lane * 2 + b2] = cse[nt * 2 + b2];
            }
        }

        #pragma unroll
        for (int s = 0; s < 4; ++s) {
            #pragma unroll
            for (int o = 1; o < 4; o <<= 1)
                se[s] += __shfl_xor_sync(0xffffffffu, se[s], o);
        }
        if (tig == 0) {
            #pragma unroll
            for (int s = 0; s < 4; ++s) se_red[wid][g][s] = se[s];
        }
        __syncthreads();

        if (tid < BM) {
            const int wm = tid >> 5;
            const int gg = (tid >> 2) & 7;
            const int ss = tid & 3;
            const int row = wm * 32 + (ss >> 1) * 16 + (ss & 1) * 8 + gg;
            g_rse[bi][it][m][row] =
                se_red[wm * 2][gg][ss] + se_red[wm * 2 + 1][gg][ss];
        } else if (m > 0) {
            const int t2 = tid - BM;
            const int wn = t2 >> 6, lc = t2 & 63;
            float cs = 0.f;
            #pragma unroll
            for (int wm = 0; wm < 4; ++wm) cs += smc[wm * 2 + wn][lc];
            g_cse[bi][j][m - 1][t2] = cs;
        }
        __syncthreads();        // protect smc/se_red/job_s before next job
    }
}

// ---------------------------------------------------------------------------
// Kernel 3: finalize. 16 slots per row, 4 per quad-sub, unrolled. Block k==0
// adds SHIFT*SEQ - |c_b|^2/256 (analytic rowsum). Elected tail does the
// deterministic final sum and resets both counters.
// ---------------------------------------------------------------------------
__global__ void __launch_bounds__(512, 2) finalize_kernel(float* __restrict__ out) {
    const int k   = blockIdx.x;
    const int b   = blockIdx.y;
    const int tid = threadIdx.x;
    const int r   = tid >> 2;
    const int sub = tid & 3;

    __shared__ float ws[16];
    __shared__ int   flag;

    const int nrow = (k < 8) ? 9 : 8;
    float seT = 0.f;
    #pragma unroll
    for (int u = 0; u < 4; ++u) {
        const int s = sub * 4 + u;          // 0..15
        const float v = (s < nrow) ? g_rse[b][k][s][r]
                                   : g_cse[b][k][s - nrow][r];
        seT += v;
    }
    #pragma unroll
    for (int o = 1; o < 4; o <<= 1)
        seT += __shfl_xor_sync(0xffffffffu, seT, o);

    float contrib = 0.f;
    if (sub == 0)
        contrib = (float)(SEQ - 1) * (SHIFT + logf(seT));

    if (k == 0) {
        float c = 0.f;
        #pragma unroll
        for (int p = 0; p < NTILE * 2; ++p) c += g_cpart[b][p][tid];
        float sqs = c * c;
        #pragma unroll
        for (int o = 1; o < 4; o <<= 1)
            sqs += __shfl_xor_sync(0xffffffffu, sqs, o);
        if (sub == 0)
            contrib += (SHIFT * (float)SEQ) * (1.0f / 128.0f) - sqs * INV256;
    }

    #pragma unroll
    for (int o = 4; o < 32; o <<= 1)
        contrib += __shfl_xor_sync(0xffffffffu, contrib, o);
    if ((tid & 31) == 0) ws[tid >> 5] = contrib;
    __syncthreads();
    if (tid < 32) {
        float v = (tid < 16) ? ws[tid] : 0.f;
        #pragma unroll
        for (int o = 8; o > 0; o >>= 1)
            v += __shfl_xor_sync(0xffffffffu, v, o);
        if (tid == 0) {
            g_partials[b * NTILE + k] = v;
            __threadfence();
            const int t = atomicAdd(&g_cnt, 1);
            flag = (t == NBLK - 1) ? 1 : 0;
        }
    }
    __syncthreads();

    if (flag) {
        if (tid < 128) {
            __threadfence();
            float v = __ldcg(&g_partials[tid]);
            #pragma unroll
            for (int o = 16; o > 0; o >>= 1)
                v += __shfl_xor_sync(0xffffffffu, v, o);
            if ((tid & 31) == 0) ws[tid >> 5] = v;
        }
        __syncthreads();
        if (tid == 0) {
            const float total = ws[0] + ws[1] + ws[2] + ws[3];
            out[0] = total * (LAMBDA / ((float)BATCH * (float)SEQ * (float)SEQ));
            g_cnt = 0;
            g_ticket = 0;            // reset persistent-GEMM ticket for replay
        }
    }
}

extern "C" void kernel_launch(void* const* d_in, const int* in_sizes, int n_in,
                              void* d_out, int out_size) {
    (void)in_sizes; (void)n_in; (void)out_size;
    const float* x = (const float*)d_in[0];
    float* out = (float*)d_out;

    cudaFuncSetAttribute(fused_mma_kernel,
                         cudaFuncAttributeMaxDynamicSharedMemorySize, SMEM_TOTAL);

    normalize_kernel<<<SEQ * BATCH / 8, 256>>>(x);
    fused_mma_kernel<<<NPERS, 256, SMEM_TOTAL>>>();
    finalize_kernel<<<dim3(NTILE, BATCH), 512>>>(out);
}

// round 14
// speedup vs baseline: 13.1063x; 1.0015x over previous
#include <cuda_runtime.h>
#include <cuda_bf16.h>
#include <cuda_fp8.h>
#include <cstdint>
#include <math.h>

#define BATCH 8
#define SEQ   2048
#define DIM   512
#define BM    128
#define BN    128
#define NKP   4
#define NTILE (SEQ / BM)
#define NBLK  (BATCH * NTILE)
#define NJOBS 136                    // per batch
#define TOTJOBS (NJOBS * BATCH)      // 1088
#define NPERS 296                    // persistent CTAs (2 per SM)
#define NNORM 148                    // normalizer-role CTAs (1 per SM)

#define SCALE8     50.59644256f
#define INV256     0.00390625f
#define SHIFT      10.0f
#define LAMBDA     0.5f

#define RSTRIDE    80
#define CTILE_B    (BM * RSTRIDE)
#define SMEM_TOTAL (8 * CTILE_B)

__device__ uint8_t g_l8[BATCH * SEQ * DIM];
__device__ float g_rse[BATCH][NTILE][9][BM];
__device__ float g_cse[BATCH][NTILE][8][BM];
__device__ float g_cpart[BATCH][NTILE * 2][DIM];
__device__ float g_partials[NBLK];
__device__ int   g_cnt;
__device__ int   g_ticket;
__device__ int   g_ready[BATCH];

__device__ __forceinline__ uint32_t smem_u32(const void* p) {
    uint32_t a;
    asm("{ .reg .u64 t; cvta.to.shared.u64 t, %1; cvt.u32.u64 %0, t; }"
        : "=r"(a) : "l"(p));
    return a;
}
__device__ __forceinline__ int ld_acquire(const int* p) {
    int v;
    asm volatile("ld.acquire.gpu.global.b32 %0, [%1];" : "=r"(v) : "l"(p));
    return v;
}
#define CP16(d, s) \
    asm volatile("cp.async.cg.shared.global [%0], [%1], 16;" :: "r"(d), "l"(s))
#define CP_COMMIT() asm volatile("cp.async.commit_group;" ::: "memory")
#define CP_WAIT(n)  asm volatile("cp.async.wait_group %0;" :: "n"(n) : "memory")

__device__ __forceinline__ void ldsm4(uint32_t* r, uint32_t addr) {
    asm volatile("ldmatrix.sync.aligned.m8n8.x4.shared.b16 {%0,%1,%2,%3}, [%4];"
                 : "=r"(r[0]), "=r"(r[1]), "=r"(r[2]), "=r"(r[3]) : "r"(addr));
}
__device__ __forceinline__ void mma16832(float* d, const uint32_t* a,
                                         uint32_t b0, uint32_t b1) {
    asm volatile(
        "mma.sync.aligned.m16n8k32.row.col.f32.e4m3.e4m3.f32 "
        "{%0,%1,%2,%3}, {%4,%5,%6,%7}, {%8,%9}, {%0,%1,%2,%3};"
        : "+f"(d[0]), "+f"(d[1]), "+f"(d[2]), "+f"(d[3])
        : "r"(a[0]), "r"(a[1]), "r"(a[2]), "r"(a[3]), "r"(b0), "r"(b1));
}
__device__ __forceinline__ float fp8_to_f32(uint8_t b) {
    __half_raw h = __nv_cvt_fp8_to_halfraw((__nv_fp8_storage_t)b, __NV_E4M3);
    return __half2float(*reinterpret_cast<__half*>(&h));
}

// ---------------------------------------------------------------------------
// Fused persistent kernel:
//  role A (blockIdx < 148): normalize batches 0..7 in order, publish per-batch
//    ready counters (fence + atomicAdd), then join the GEMM job loop.
//  role B (blockIdx >= 148): GEMM job loop from the start; tid0 acquire-spins
//    until the job's batch is normalized.
// Diagonal jobs (m==0) also emit half-block column sums (bit-identical to the
// old colsum kernel). All result slots are job-keyed -> deterministic.
// ---------------------------------------------------------------------------
__global__ void __launch_bounds__(256, 2) fused_all_kernel(
        const float* __restrict__ x) {
    extern __shared__ char smem[];
    const uint32_t sb  = smem_u32(smem);
    const int tid  = threadIdx.x;
    const int wid  = tid >> 5;
    const int lane = tid & 31;
    const int warp_m = wid >> 1;
    const int warp_n = wid & 1;

    const int g   = lane >> 2;
    const int tig = lane & 3;
    const int lrow = lane & 15;
    const int lsel = (lane >> 4) & 1;

    __shared__ int   job_s;
    __shared__ float smc[8][64];
    __shared__ float se_red[8][8][4];

    // ---------------- role A: normalize ----------------
    if (blockIdx.x < NNORM) {
        const int c = blockIdx.x;
        for (int b = 0; b < BATCH; ++b) {
            for (int idx = c + NNORM * wid; idx < SEQ; idx += NNORM * 8) {
                const int row = b * SEQ + idx;
                const float4* __restrict__ xr =
                    reinterpret_cast<const float4*>(x + (size_t)row * DIM)
                    + lane * 4;
                float4 v[4];
                float ss = 0.f;
                #pragma unroll
                for (int q = 0; q < 4; ++q) {
                    v[q] = xr[q];
                    ss = fmaf(v[q].x, v[q].x, ss);
                    ss = fmaf(v[q].y, v[q].y, ss);
                    ss = fmaf(v[q].z, v[q].z, ss);
                    ss = fmaf(v[q].w, v[q].w, ss);
                }
                #pragma unroll
                for (int o = 16; o > 0; o >>= 1)
                    ss += __shfl_xor_sync(0xffffffffu, ss, o);
                const float inv = SCALE8 / fmaxf(sqrtf(ss), 1e-8f);
                uint32_t w[4];
                #pragma unroll
                for (int q = 0; q < 4; ++q) {
                    const __nv_fp8x2_storage_t p01 = __nv_cvt_float2_to_fp8x2(
                        make_float2(v[q].x * inv, v[q].y * inv),
                        __NV_SATFINITE, __NV_E4M3);
                    const __nv_fp8x2_storage_t p23 = __nv_cvt_float2_to_fp8x2(
                        make_float2(v[q].z * inv, v[q].w * inv),
                        __NV_SATFINITE, __NV_E4M3);
                    w[q] = (uint32_t)p01 | ((uint32_t)p23 << 16);
                }
                uint4 o4;
                o4.x = w[0]; o4.y = w[1]; o4.z = w[2]; o4.w = w[3];
                *reinterpret_cast<uint4*>(
                    g_l8 + (size_t)row * DIM + lane * 16) = o4;
            }
            __syncthreads();
            if (tid == 0) {
                __threadfence();
                const int cnt = (SEQ - 1 - c) / NNORM + 1;
                atomicAdd(&g_ready[b], cnt);
            }
        }
    }

    // ---------------- GEMM job loop (both roles) ----------------
    for (;;) {
        if (tid == 0) {
            const int job = atomicAdd(&g_ticket, 1);
            job_s = job;
            if (job < TOTJOBS) {
                const int bi = job / NJOBS;
                while (ld_acquire(&g_ready[bi]) < SEQ) __nanosleep(64);
            }
        }
        __syncthreads();
        const int job = job_s;
        if (job >= TOTJOBS) break;

        const int bi = job / NJOBS;
        const int jx = job - bi * NJOBS;
        int it, m;
        if (jx < 72) { it = jx / 9; m = jx % 9; }
        else { const int t2 = jx - 72; it = 8 + t2 / 8; m = t2 % 8; }
        const int j = (it + m) & 15;

        const uint8_t* __restrict__ base = g_l8 + (size_t)bi * SEQ * DIM;
        const uint8_t* __restrict__ Ab   = base + (size_t)(it * BM) * DIM;
        const uint8_t* __restrict__ Bb   = base + (size_t)(j * BN) * DIM;

        auto load_stage = [&](int stage, int kp) {
            const uint32_t sbase = sb + stage * 4 * CTILE_B;
            #pragma unroll
            for (int u = 0; u < 8; ++u) {
                const int p  = tid + u * 256;
                const int ch = p >> 9;
                const int rem = p & 511;
                const int r = rem >> 2, c = rem & 3;
                const uint8_t* src = (ch < 2 ? Ab : Bb)
                    + (size_t)r * DIM + kp * 128 + (ch & 1) * 64 + c * 16;
                CP16(sbase + ch * CTILE_B + r * RSTRIDE + c * 16, src);
            }
            CP_COMMIT();
        };

        load_stage(0, 0);

        float acc[2][8][4];
        #pragma unroll
        for (int mt = 0; mt < 2; ++mt)
            #pragma unroll
            for (int nt = 0; nt < 8; ++nt)
                #pragma unroll
                for (int i = 0; i < 4; ++i) acc[mt][nt][i] = 0.f;

        for (int kp = 0; kp < NKP; ++kp) {
            if (kp + 1 < NKP) {
                load_stage((kp + 1) & 1, kp + 1);
                CP_WAIT(1);
            } else {
                CP_WAIT(0);
            }
            __syncthreads();

            #pragma unroll
            for (int cc = 0; cc < 2; ++cc) {
                const uint32_t abase = sb + ((kp & 1) * 4 + cc) * CTILE_B;
                const uint32_t bbase = sb + ((kp & 1) * 4 + 2 + cc) * CTILE_B;
                #pragma unroll
                for (int ks = 0; ks < 2; ++ks) {
                    uint32_t af[2][4];
                    #pragma unroll
                    for (int mt = 0; mt < 2; ++mt)
                        ldsm4(af[mt], abase
                              + (warp_m * 32 + mt * 16 + lrow) * RSTRIDE
                              + ks * 32 + lsel * 16);
                    uint32_t bx[4][4];
                    #pragma unroll
                    for (int q = 0; q < 4; ++q)
                        ldsm4(bx[q], bbase
                              + (warp_n * 64 + q * 16 + lrow) * RSTRIDE
                              + ks * 32 + lsel * 16);
                    #pragma unroll
                    for (int mt = 0; mt < 2; ++mt)
                        #pragma unroll
                        for (int nt = 0; nt < 8; ++nt) {
                            const int q = nt >> 1, e = nt & 1;
                            mma16832(acc[mt][nt], af[mt], bx[q][e], bx[q][e + 2]);
                        }
                }
            }

            // fused column-sum partials (diagonal jobs only)
            if (m == 0) {
                const int half = tid >> 7;
                const int col  = tid & 127;
                const size_t off = (size_t)((kp & 1) * 4 + (col >> 6)) * CTILE_B
                                 + (size_t)(half * 64) * RSTRIDE + (col & 63);
                float s = 0.f;
                #pragma unroll 8
                for (int r2 = 0; r2 < 64; ++r2)
                    s += fp8_to_f32((uint8_t)smem[off + (size_t)r2 * RSTRIDE]);
                g_cpart[bi][it * 2 + half][kp * 128 + col] = s;
            }
            __syncthreads();
        }

        // fused two-sided epilogue (sumexp only; v = acc/256)
        float se[4];
        #pragma unroll
        for (int s = 0; s < 4; ++s) se[s] = 0.f;

        if (m == 0) {
            #pragma unroll
            for (int mt = 0; mt < 2; ++mt)
                #pragma unroll
                for (int nt = 0; nt < 8; ++nt)
                    #pragma unroll
                    for (int i = 0; i < 4; ++i) {
                        const int lr = warp_m * 32 + mt * 16 + (i >> 1) * 8 + g;
                        const int lc = warp_n * 64 + nt * 8 + tig * 2 + (i & 1);
                        if (lr != lc)
                            se[mt * 2 + (i >> 1)] +=
                                __expf(fmaf(acc[mt][nt][i], INV256, -SHIFT));
                    }
        } else {
            float cse[16];
            #pragma unroll
            for (int q = 0; q < 16; ++q) cse[q] = 0.f;
            #pragma unroll
            for (int mt = 0; mt < 2; ++mt)
                #pragma unroll
                for (int nt = 0; nt < 8; ++nt)
                    #pragma unroll
                    for (int i = 0; i < 4; ++i) {
                        const float e =
                            __expf(fmaf(acc[mt][nt][i], INV256, -SHIFT));
                        se[mt * 2 + (i >> 1)] += e;
                        cse[nt * 2 + (i & 1)] += e;
                    }
            #pragma unroll
            for (int q = 0; q < 16; ++q) {
                #pragma unroll
                for (int o = 4; o < 32; o <<= 1)
                    cse[q] += __shfl_xor_sync(0xffffffffu, cse[q], o);
            }
            if (lane < 4) {
                #pragma unroll
                for (int nt = 0; nt < 8; ++nt)
                    #pragma unroll
                    for (int b2 = 0; b2 < 2; ++b2)
                        smc[wid][nt * 8 + lane * 2 + b2] = cse[nt * 2 + b2];
            }
        }

        #pragma unroll
        for (int s = 0; s < 4; ++s) {
            #pragma unroll
            for (int o = 1; o < 4; o <<= 1)
                se[s] += __shfl_xor_sync(0xffffffffu, se[s], o);
        }
        if (tig == 0) {
            #pragma unroll
            for (int s = 0; s < 4; ++s) se_red[wid][g][s] = se[s];
        }
        __syncthreads();

        if (tid < BM) {
            const int wm = tid >> 5;
            const int gg = (tid >> 2) & 7;
            const int ss = tid & 3;
            const int row = wm * 32 + (ss >> 1) * 16 + (ss & 1) * 8 + gg;
            g_rse[bi][it][m][row] =
                se_red[wm * 2][gg][ss] + se_red[wm * 2 + 1][gg][ss];
        } else if (m > 0) {
            const int t2 = tid - BM;
            const int wn = t2 >> 6, lc = t2 & 63;
            float cs = 0.f;
            #pragma unroll
            for (int wm = 0; wm < 4; ++wm) cs += smc[wm * 2 + wn][lc];
            g_cse[bi][j][m - 1][t2] = cs;
        }
        __syncthreads();        // protect smc/se_red/job_s before next job
    }
}

// ---------------------------------------------------------------------------
// Finalize: 16 slots per row, 4 per quad-sub, unrolled. Block k==0 adds
// SHIFT*SEQ - |c_b|^2/256. Elected tail does the deterministic final sum and
// resets all counters for graph replay.
// ---------------------------------------------------------------------------
__global__ void __launch_bounds__(512, 2) finalize_kernel(float* __restrict__ out) {
    const int k   = blockIdx.x;
    const int b   = blockIdx.y;
    const int tid = threadIdx.x;
    const int r   = tid >> 2;
    const int sub = tid & 3;

    __shared__ float ws[16];
    __shared__ int   flag;

    const int nrow = (k < 8) ? 9 : 8;
    float seT = 0.f;
    #pragma unroll
    for (int u = 0; u < 4; ++u) {
        const int s = sub * 4 + u;
        const float v = (s < nrow) ? g_rse[b][k][s][r]
                                   : g_cse[b][k][s - nrow][r];
        seT += v;
    }
    #pragma unroll
    for (int o = 1; o < 4; o <<= 1)
        seT += __shfl_xor_sync(0xffffffffu, seT, o);

    float contrib = 0.f;
    if (sub == 0)
        contrib = (float)(SEQ - 1) * (SHIFT + logf(seT));

    if (k == 0) {
        float c = 0.f;
        #pragma unroll
        for (int p = 0; p < NTILE * 2; ++p) c += g_cpart[b][p][tid];
        float sqs = c * c;
        #pragma unroll
        for (int o = 1; o < 4; o <<= 1)
            sqs += __shfl_xor_sync(0xffffffffu, sqs, o);
        if (sub == 0)
            contrib += (SHIFT * (float)SEQ) * (1.0f / 128.0f) - sqs * INV256;
    }

    #pragma unroll
    for (int o = 4; o < 32; o <<= 1)
        contrib += __shfl_xor_sync(0xffffffffu, contrib, o);
    if ((tid & 31) == 0) ws[tid >> 5] = contrib;
    __syncthreads();
    if (tid < 32) {
        float v = (tid < 16) ? ws[tid] : 0.f;
        #pragma unroll
        for (int o = 8; o > 0; o >>= 1)
            v += __shfl_xor_sync(0xffffffffu, v, o);
        if (tid == 0) {
            g_partials[b * NTILE + k] = v;
            __threadfence();
            const int t = atomicAdd(&g_cnt, 1);
            flag = (t == NBLK - 1) ? 1 : 0;
        }
    }
    __syncthreads();

    if (flag) {
        if (tid < 128) {
            __threadfence();
            float v = __ldcg(&g_partials[tid]);
            #pragma unroll
            for (int o = 16; o > 0; o >>= 1)
                v += __shfl_xor_sync(0xffffffffu, v, o);
            if ((tid & 31) == 0) ws[tid >> 5] = v;
        }
        __syncthreads();
        if (tid == 0) {
            const float total = ws[0] + ws[1] + ws[2] + ws[3];
            out[0] = total * (LAMBDA / ((float)BATCH * (float)SEQ * (float)SEQ));
            g_cnt = 0;
            g_ticket = 0;
            #pragma unroll
            for (int b2 = 0; b2 < BATCH; ++b2) g_ready[b2] = 0;
        }
    }
}

extern "C" void kernel_launch(void* const* d_in, const int* in_sizes, int n_in,
                              void* d_out, int out_size) {
    (void)in_sizes; (void)n_in; (void)out_size;
    const float* x = (const float*)d_in[0];
    float* out = (float*)d_out;

    cudaFuncSetAttribute(fused_all_kernel,
                         cudaFuncAttributeMaxDynamicSharedMemorySize, SMEM_TOTAL);

    fused_all_kernel<<<NPERS, 256, SMEM_TOTAL>>>(x);
    finalize_kernel<<<dim3(NTILE, BATCH), 512>>>(out);
}